// round 3
// baseline (speedup 1.0000x reference)
#include <cuda_runtime.h>
#include <math.h>

// Problem dims
#define BATCH   8
#define SEQ     1024
#define NEMBD   1024
#define NHEAD   16
#define HSIZE   64
#define FFDIM   4096
#define ROWS    (BATCH * SEQ)          // 8192
#define QKVCOLS (3 * NEMBD)            // 3072

// ---------------- scratch (device globals; no allocation allowed) ----------
__device__ float g_xn1[ROWS * NEMBD];       // LN1 output (also residual base)
__device__ float g_wqkv[NEMBD * QKVCOLS];   // repacked [D, 3*H*E] weight
__device__ float g_qkv[ROWS * QKVCOLS];     // q|k|v, row = b*T+t, col = sec*1024 + h*64 + e
__device__ float g_attn[ROWS * NEMBD];      // attention output (heads concatenated)
__device__ float g_x2[ROWS * NEMBD];        // after proj + residual
__device__ float g_xn2[ROWS * NEMBD];       // LN2 output (residual base for FFN)
__device__ float g_h[ROWS * FFDIM];         // FFN hidden

// ---------------- weight repack: wq/wk/wv [H,D,E] -> Wqkv [D, 3072] --------
__global__ void repack_qkv_kernel(const float* __restrict__ wq,
                                  const float* __restrict__ wk,
                                  const float* __restrict__ wv,
                                  float* __restrict__ W) {
    int idx = blockIdx.x * 256 + threadIdx.x;
    if (idx >= NEMBD * QKVCOLS) return;
    int d = idx / QKVCOLS;
    int j = idx - d * QKVCOLS;
    int sec = j >> 10;            // 0=q 1=k 2=v
    int within = j & 1023;
    int h = within >> 6;
    int e = within & 63;
    const float* src = (sec == 0) ? wq : (sec == 1) ? wk : wv;
    W[idx] = src[((size_t)h * NEMBD + d) * HSIZE + e];
}

// ---------------- LayerNorm: one block (256 thr) per row -------------------
__global__ void ln_kernel(const float* __restrict__ in, float* __restrict__ out,
                          const float* __restrict__ gamma, const float* __restrict__ beta) {
    int row = blockIdx.x;
    const float4* x4 = (const float4*)(in + (size_t)row * NEMBD);
    int i = threadIdx.x;                       // 256 threads, 256 float4 per row
    float4 a = x4[i];
    float s  = a.x + a.y + a.z + a.w;
    float s2 = a.x * a.x + a.y * a.y + a.z * a.z + a.w * a.w;

    #pragma unroll
    for (int o = 16; o; o >>= 1) {
        s  += __shfl_xor_sync(0xffffffffu, s, o);
        s2 += __shfl_xor_sync(0xffffffffu, s2, o);
    }
    __shared__ float sh[2][8];
    __shared__ float stats[2];
    int lane = threadIdx.x & 31, wid = threadIdx.x >> 5;
    if (lane == 0) { sh[0][wid] = s; sh[1][wid] = s2; }
    __syncthreads();
    if (threadIdx.x == 0) {
        float ts = 0.f, ts2 = 0.f;
        #pragma unroll
        for (int w = 0; w < 8; w++) { ts += sh[0][w]; ts2 += sh[1][w]; }
        float mu  = ts * (1.f / NEMBD);
        float var = ts2 * (1.f / NEMBD) - mu * mu;
        stats[0] = mu;
        stats[1] = rsqrtf(var + 1e-5f);
    }
    __syncthreads();
    float mu = stats[0], inv = stats[1];
    float4 g = ((const float4*)gamma)[i];
    float4 b = ((const float4*)beta)[i];
    float4 r;
    r.x = (a.x - mu) * inv * g.x + b.x;
    r.y = (a.y - mu) * inv * g.y + b.y;
    r.z = (a.z - mu) * inv * g.z + b.z;
    r.w = (a.w - mu) * inv * g.w + b.w;
    ((float4*)(out + (size_t)row * NEMBD))[i] = r;
}

// ---------------- SGEMM 128x128x8, 256 threads, 8x8 microtile --------------
// C[M,N] = A[M,K](row-major) * B[K,N](row-major)  (+bias) (+res) (relu?)
__global__ void __launch_bounds__(256)
sgemm_kernel(const float* __restrict__ A, const float* __restrict__ B,
             float* __restrict__ C, int M, int N, int K,
             const float* __restrict__ bias, const float* __restrict__ res, int relu) {
    __shared__ float As[8][128];
    __shared__ float Bs[8][128];

    int bx = blockIdx.x;   // col tile
    int by = blockIdx.y;   // row tile
    int tid = threadIdx.x;
    int tx = tid & 15;
    int ty = tid >> 4;

    const float* Ab = A + (size_t)by * 128 * K;
    const float* Bb = B + (size_t)bx * 128;

    int aRow = tid >> 1;          // 0..127
    int aCol = (tid & 1) * 4;     // 0 or 4
    int bRow = tid >> 5;          // 0..7
    int bCol = (tid & 31) * 4;    // 0..124

    float acc[8][8];
    #pragma unroll
    for (int i = 0; i < 8; i++)
        #pragma unroll
        for (int j = 0; j < 8; j++) acc[i][j] = 0.f;

    for (int k0 = 0; k0 < K; k0 += 8) {
        float4 a4 = *(const float4*)(Ab + (size_t)aRow * K + k0 + aCol);
        As[aCol + 0][aRow] = a4.x;
        As[aCol + 1][aRow] = a4.y;
        As[aCol + 2][aRow] = a4.z;
        As[aCol + 3][aRow] = a4.w;
        *(float4*)&Bs[bRow][bCol] = *(const float4*)(Bb + (size_t)(k0 + bRow) * N + bCol);
        __syncthreads();

        #pragma unroll
        for (int k = 0; k < 8; k++) {
            float4 a0 = *(const float4*)&As[k][ty * 8];
            float4 a1 = *(const float4*)&As[k][ty * 8 + 4];
            float4 b0 = *(const float4*)&Bs[k][tx * 8];
            float4 b1 = *(const float4*)&Bs[k][tx * 8 + 4];
            float ar[8] = {a0.x, a0.y, a0.z, a0.w, a1.x, a1.y, a1.z, a1.w};
            float br[8] = {b0.x, b0.y, b0.z, b0.w, b1.x, b1.y, b1.z, b1.w};
            #pragma unroll
            for (int i = 0; i < 8; i++)
                #pragma unroll
                for (int j = 0; j < 8; j++) acc[i][j] += ar[i] * br[j];
        }
        __syncthreads();
    }

    #pragma unroll
    for (int i = 0; i < 8; i++) {
        int row = by * 128 + ty * 8 + i;
        #pragma unroll
        for (int j = 0; j < 8; j++) {
            int col = bx * 128 + tx * 8 + j;
            float v = acc[i][j];
            if (bias) v += bias[col];
            if (res)  v += res[(size_t)row * N + col];
            if (relu) v = fmaxf(v, 0.f);
            C[(size_t)row * N + col] = v;
        }
    }
}

// ---------------- causal flash attention --------------------------------
// grid (qtile=16, head=16, batch=8), 64 threads; thread r owns query row qtile*64+r.
__global__ void __launch_bounds__(64)
attn_kernel(const float* __restrict__ qkv, float* __restrict__ outp) {
    int qt = blockIdx.x;
    int h  = blockIdx.y;
    int b  = blockIdx.z;
    int r  = threadIdx.x;

    __shared__ float ks[64][68];
    __shared__ float vs[64][68];

    int qi = qt * 64 + r;
    const float* qrow = qkv + ((size_t)(b * SEQ + qi)) * QKVCOLS + h * 64;
    float q[64];
    #pragma unroll
    for (int e = 0; e < 64; e++) q[e] = qrow[e];

    float o[64];
    #pragma unroll
    for (int e = 0; e < 64; e++) o[e] = 0.f;
    float m = -1e30f, l = 0.f;

    for (int kt = 0; kt <= qt; kt++) {
        const float* kbase = qkv + ((size_t)(b * SEQ + kt * 64)) * QKVCOLS + NEMBD + h * 64;
        const float* vbase = kbase + NEMBD;
        #pragma unroll 8
        for (int i = 0; i < 64; i++) {
            ks[i][r] = kbase[(size_t)i * QKVCOLS + r];
            vs[i][r] = vbase[(size_t)i * QKVCOLS + r];
        }
        __syncthreads();

        int jmax = (kt == qt) ? r : 63;     // causal: key index within tile must be <= jmax
        for (int jc = 0; jc < 64; jc += 8) {
            if (jc > jmax) break;
            float sv[8];
            #pragma unroll
            for (int u = 0; u < 8; u++) {
                float sj = 0.f;
                #pragma unroll
                for (int e = 0; e < 64; e += 4) {
                    float4 kk = *(const float4*)&ks[jc + u][e];
                    sj += q[e] * kk.x + q[e + 1] * kk.y + q[e + 2] * kk.z + q[e + 3] * kk.w;
                }
                sv[u] = (jc + u > jmax) ? -1e30f : sj * 0.125f;
            }
            float mt = m;
            #pragma unroll
            for (int u = 0; u < 8; u++) mt = fmaxf(mt, sv[u]);
            float sc = __expf(m - mt);
            m = mt;
            l *= sc;
            float p[8];
            float ps = 0.f;
            #pragma unroll
            for (int u = 0; u < 8; u++) { p[u] = __expf(sv[u] - mt); ps += p[u]; }
            l += ps;
            #pragma unroll
            for (int e = 0; e < 64; e += 4) {
                float ax = o[e] * sc, ay = o[e+1] * sc, az = o[e+2] * sc, aw = o[e+3] * sc;
                #pragma unroll
                for (int u = 0; u < 8; u++) {
                    float4 vv = *(const float4*)&vs[jc + u][e];
                    ax += p[u] * vv.x; ay += p[u] * vv.y;
                    az += p[u] * vv.z; aw += p[u] * vv.w;
                }
                o[e] = ax; o[e+1] = ay; o[e+2] = az; o[e+3] = aw;
            }
        }
        __syncthreads();
    }

    float inv = 1.f / l;
    float* orow = outp + ((size_t)(b * SEQ + qi)) * NEMBD + h * 64;
    #pragma unroll
    for (int e = 0; e < 64; e++) orow[e] = o[e] * inv;
}

// ---------------- launch ---------------------------------------------------
extern "C" void kernel_launch(void* const* d_in, const int* in_sizes, int n_in,
                              void* d_out, int out_size) {
    const float* x      = (const float*)d_in[0];
    const float* wq     = (const float*)d_in[1];
    const float* wk     = (const float*)d_in[2];
    const float* wv     = (const float*)d_in[3];
    const float* w_proj = (const float*)d_in[4];
    const float* b_proj = (const float*)d_in[5];
    const float* w1     = (const float*)d_in[6];
    const float* b1     = (const float*)d_in[7];
    const float* w2     = (const float*)d_in[8];
    const float* b2     = (const float*)d_in[9];
    const float* g1     = (const float*)d_in[10];
    const float* be1    = (const float*)d_in[11];
    const float* g2     = (const float*)d_in[12];
    const float* be2    = (const float*)d_in[13];
    float* out = (float*)d_out;

    float *p_xn1, *p_wqkv, *p_qkv, *p_attn, *p_x2, *p_xn2, *p_h;
    cudaGetSymbolAddress((void**)&p_xn1,  g_xn1);
    cudaGetSymbolAddress((void**)&p_wqkv, g_wqkv);
    cudaGetSymbolAddress((void**)&p_qkv,  g_qkv);
    cudaGetSymbolAddress((void**)&p_attn, g_attn);
    cudaGetSymbolAddress((void**)&p_x2,   g_x2);
    cudaGetSymbolAddress((void**)&p_xn2,  g_xn2);
    cudaGetSymbolAddress((void**)&p_h,    g_h);

    // 1. repack qkv weights
    repack_qkv_kernel<<<(NEMBD * QKVCOLS + 255) / 256, 256>>>(wq, wk, wv, p_wqkv);
    // 2. LN1
    ln_kernel<<<ROWS, 256>>>(x, p_xn1, g1, be1);
    // 3. QKV projection: [8192,1024] @ [1024,3072]
    sgemm_kernel<<<dim3(QKVCOLS / 128, ROWS / 128), 256>>>(
        p_xn1, p_wqkv, p_qkv, ROWS, QKVCOLS, NEMBD, nullptr, nullptr, 0);
    // 4. causal attention
    attn_kernel<<<dim3(SEQ / 64, NHEAD, BATCH), 64>>>(p_qkv, p_attn);
    // 5. output projection + bias + residual(xn1)
    sgemm_kernel<<<dim3(NEMBD / 128, ROWS / 128), 256>>>(
        p_attn, w_proj, p_x2, ROWS, NEMBD, NEMBD, b_proj, p_xn1, 0);
    // 6. LN2
    ln_kernel<<<ROWS, 256>>>(p_x2, p_xn2, g2, be2);
    // 7. FFN up + bias + relu
    sgemm_kernel<<<dim3(FFDIM / 128, ROWS / 128), 256>>>(
        p_xn2, w1, p_h, ROWS, FFDIM, NEMBD, b1, nullptr, 1);
    // 8. FFN down + bias + residual(xn2) -> final output
    sgemm_kernel<<<dim3(NEMBD / 128, ROWS / 128), 256>>>(
        p_h, w2, out, ROWS, NEMBD, FFDIM, b2, p_xn2, 0);
}

// round 5
// speedup vs baseline: 2.9126x; 2.9126x over previous
#include <cuda_runtime.h>
#include <cuda_bf16.h>
#include <math.h>
#include <stdint.h>

// Problem dims
#define BATCH   8
#define SEQ     1024
#define NEMBD   1024
#define NHEAD   16
#define HSIZE   64
#define FFDIM   4096
#define ROWS    (BATCH * SEQ)          // 8192
#define QKVCOLS (3 * NEMBD)            // 3072

// ---------------- scratch (device globals; no allocation allowed) ----------
__device__ float g_xn1[ROWS * NEMBD];
__device__ float g_wqkv[NEMBD * QKVCOLS];
__device__ float g_qkv[ROWS * QKVCOLS];
__device__ float g_attn[ROWS * NEMBD];
__device__ float g_x2[ROWS * NEMBD];
__device__ float g_xn2[ROWS * NEMBD];
__device__ float g_h[ROWS * FFDIM];

// ---------------- weight repack: wq/wk/wv [H,D,E] -> Wqkv [D, 3072] --------
__global__ void repack_qkv_kernel(const float* __restrict__ wq,
                                  const float* __restrict__ wk,
                                  const float* __restrict__ wv,
                                  float* __restrict__ W) {
    int idx = blockIdx.x * 256 + threadIdx.x;
    if (idx >= NEMBD * QKVCOLS) return;
    int d = idx / QKVCOLS;
    int j = idx - d * QKVCOLS;
    int sec = j >> 10;
    int within = j & 1023;
    int h = within >> 6;
    int e = within & 63;
    const float* src = (sec == 0) ? wq : (sec == 1) ? wk : wv;
    W[idx] = src[((size_t)h * NEMBD + d) * HSIZE + e];
}

// ---------------- LayerNorm -------------------------------------------------
__global__ void ln_kernel(const float* __restrict__ in, float* __restrict__ out,
                          const float* __restrict__ gamma, const float* __restrict__ beta) {
    int row = blockIdx.x;
    const float4* x4 = (const float4*)(in + (size_t)row * NEMBD);
    int i = threadIdx.x;
    float4 a = x4[i];
    float s  = a.x + a.y + a.z + a.w;
    float s2 = a.x * a.x + a.y * a.y + a.z * a.z + a.w * a.w;

    #pragma unroll
    for (int o = 16; o; o >>= 1) {
        s  += __shfl_xor_sync(0xffffffffu, s, o);
        s2 += __shfl_xor_sync(0xffffffffu, s2, o);
    }
    __shared__ float sh[2][8];
    __shared__ float stats[2];
    int lane = threadIdx.x & 31, wid = threadIdx.x >> 5;
    if (lane == 0) { sh[0][wid] = s; sh[1][wid] = s2; }
    __syncthreads();
    if (threadIdx.x == 0) {
        float ts = 0.f, ts2 = 0.f;
        #pragma unroll
        for (int w = 0; w < 8; w++) { ts += sh[0][w]; ts2 += sh[1][w]; }
        float mu  = ts * (1.f / NEMBD);
        float var = ts2 * (1.f / NEMBD) - mu * mu;
        stats[0] = mu;
        stats[1] = rsqrtf(var + 1e-5f);
    }
    __syncthreads();
    float mu = stats[0], inv = stats[1];
    float4 g = ((const float4*)gamma)[i];
    float4 b = ((const float4*)beta)[i];
    float4 r;
    r.x = (a.x - mu) * inv * g.x + b.x;
    r.y = (a.y - mu) * inv * g.y + b.y;
    r.z = (a.z - mu) * inv * g.z + b.z;
    r.w = (a.w - mu) * inv * g.w + b.w;
    ((float4*)(out + (size_t)row * NEMBD))[i] = r;
}

// ---------------- tensor-core GEMM (bf16 2-term split, fp32 accuracy) -------
// C[M,N] = A[M,K] * B[K,N], all row-major fp32; (+bias)(+res)(relu?)
// Block 256 thr = 8 warps (2x4), tile 128x128, K-step 32, mma.m16n8k16.bf16.

__device__ __forceinline__ uint32_t smem_u32(const void* p) {
    return (uint32_t)__cvta_generic_to_shared(p);
}
__device__ __forceinline__ void ldsm_x4(uint32_t* r, uint32_t addr) {
    asm volatile("ldmatrix.sync.aligned.m8n8.x4.shared.b16 {%0,%1,%2,%3}, [%4];"
                 : "=r"(r[0]), "=r"(r[1]), "=r"(r[2]), "=r"(r[3]) : "r"(addr));
}
__device__ __forceinline__ void ldsm_x2t(uint32_t* r, uint32_t addr) {
    asm volatile("ldmatrix.sync.aligned.m8n8.x2.trans.shared.b16 {%0,%1}, [%2];"
                 : "=r"(r[0]), "=r"(r[1]) : "r"(addr));
}
__device__ __forceinline__ void mma16816(float* c, const uint32_t* a, const uint32_t* b) {
    asm volatile("mma.sync.aligned.m16n8k16.row.col.f32.bf16.bf16.f32 "
                 "{%0,%1,%2,%3}, {%4,%5,%6,%7}, {%8,%9}, {%0,%1,%2,%3};"
                 : "+f"(c[0]), "+f"(c[1]), "+f"(c[2]), "+f"(c[3])
                 : "r"(a[0]), "r"(a[1]), "r"(a[2]), "r"(a[3]),
                   "r"(b[0]), "r"(b[1]));
}
__device__ __forceinline__ uint32_t pack2(__nv_bfloat16 a, __nv_bfloat16 b) {
    return (uint32_t)__bfloat16_as_ushort(a) | ((uint32_t)__bfloat16_as_ushort(b) << 16);
}
// split float4 into hi/lo bf16 pairs and store (8B each)
__device__ __forceinline__ void store_split(__nv_bfloat16* ph, __nv_bfloat16* pl, float4 v) {
    __nv_bfloat16 hx = __float2bfloat16_rn(v.x);
    __nv_bfloat16 hy = __float2bfloat16_rn(v.y);
    __nv_bfloat16 hz = __float2bfloat16_rn(v.z);
    __nv_bfloat16 hw = __float2bfloat16_rn(v.w);
    __nv_bfloat16 lx = __float2bfloat16_rn(v.x - __bfloat162float(hx));
    __nv_bfloat16 ly = __float2bfloat16_rn(v.y - __bfloat162float(hy));
    __nv_bfloat16 lz = __float2bfloat16_rn(v.z - __bfloat162float(hz));
    __nv_bfloat16 lw = __float2bfloat16_rn(v.w - __bfloat162float(hw));
    *(uint2*)ph = make_uint2(pack2(hx, hy), pack2(hz, hw));
    *(uint2*)pl = make_uint2(pack2(lx, ly), pack2(lz, lw));
}

#define APAD 40    // 32 + 8 bf16 pad (80B stride, ldmatrix conflict-free)
#define BPAD 136   // 128 + 8 bf16 pad (272B stride, conflict-free for trans)

__global__ void __launch_bounds__(256)
tcgemm_kernel(const float* __restrict__ A, const float* __restrict__ B,
              float* __restrict__ C, int M, int N, int K,
              const float* __restrict__ bias, const float* __restrict__ res, int relu) {
    __shared__ __nv_bfloat16 As_h[128][APAD];
    __shared__ __nv_bfloat16 As_l[128][APAD];
    __shared__ __nv_bfloat16 Bs_h[32][BPAD];
    __shared__ __nv_bfloat16 Bs_l[32][BPAD];

    int bx = blockIdx.x, by = blockIdx.y;
    int tid = threadIdx.x;
    int lane = tid & 31, warp = tid >> 5;
    int wm = (warp >> 2) * 64;    // warp row offset within 128-tile
    int wn = (warp & 3) * 32;     // warp col offset

    float acc[4][4][4];
    #pragma unroll
    for (int mi = 0; mi < 4; mi++)
        #pragma unroll
        for (int ni = 0; ni < 4; ni++)
            #pragma unroll
            for (int q = 0; q < 4; q++) acc[mi][ni][q] = 0.f;

    float4 aReg[4], bReg[4];

    // prefetch tile 0
    #pragma unroll
    for (int i = 0; i < 4; i++) {
        int idx = tid + i * 256;
        int rowA = idx >> 3, c4A = idx & 7;
        aReg[i] = *(const float4*)(A + (size_t)(by * 128 + rowA) * K + c4A * 4);
        int rowB = idx >> 5, c4B = idx & 31;
        bReg[i] = *(const float4*)(B + (size_t)rowB * N + bx * 128 + c4B * 4);
    }

    int ntiles = K / 32;
    for (int t = 0; t < ntiles; t++) {
        // regs -> smem (with split conversion)
        #pragma unroll
        for (int i = 0; i < 4; i++) {
            int idx = tid + i * 256;
            int rowA = idx >> 3, c4A = idx & 7;
            store_split(&As_h[rowA][c4A * 4], &As_l[rowA][c4A * 4], aReg[i]);
            int rowB = idx >> 5, c4B = idx & 31;
            store_split(&Bs_h[rowB][c4B * 4], &Bs_l[rowB][c4B * 4], bReg[i]);
        }
        __syncthreads();

        // prefetch next tile while computing this one
        if (t + 1 < ntiles) {
            int k0 = (t + 1) * 32;
            #pragma unroll
            for (int i = 0; i < 4; i++) {
                int idx = tid + i * 256;
                int rowA = idx >> 3, c4A = idx & 7;
                aReg[i] = *(const float4*)(A + (size_t)(by * 128 + rowA) * K + k0 + c4A * 4);
                int rowB = idx >> 5, c4B = idx & 31;
                bReg[i] = *(const float4*)(B + (size_t)(k0 + rowB) * N + bx * 128 + c4B * 4);
            }
        }

        // compute: 2 x k16 steps
        #pragma unroll
        for (int kk = 0; kk < 2; kk++) {
            int kb = kk * 16;
            uint32_t bh[4][2], bl[4][2];
            #pragma unroll
            for (int ni = 0; ni < 4; ni++) {
                ldsm_x2t(bh[ni], smem_u32(&Bs_h[kb + (lane & 15)][wn + ni * 8]));
                ldsm_x2t(bl[ni], smem_u32(&Bs_l[kb + (lane & 15)][wn + ni * 8]));
            }
            #pragma unroll
            for (int mi = 0; mi < 4; mi++) {
                uint32_t ah[4], al[4];
                ldsm_x4(ah, smem_u32(&As_h[wm + mi * 16 + (lane & 15)][kb + (lane >> 4) * 8]));
                ldsm_x4(al, smem_u32(&As_l[wm + mi * 16 + (lane & 15)][kb + (lane >> 4) * 8]));
                #pragma unroll
                for (int ni = 0; ni < 4; ni++) {
                    mma16816(acc[mi][ni], ah, bh[ni]);   // hi*hi
                    mma16816(acc[mi][ni], ah, bl[ni]);   // hi*lo
                    mma16816(acc[mi][ni], al, bh[ni]);   // lo*hi
                }
            }
        }
        __syncthreads();
    }

    // epilogue
    int g = lane >> 2, tig = lane & 3;
    #pragma unroll
    for (int mi = 0; mi < 4; mi++) {
        #pragma unroll
        for (int ni = 0; ni < 4; ni++) {
            int r0 = by * 128 + wm + mi * 16 + g;
            int c0 = bx * 128 + wn + ni * 8 + tig * 2;
            float b0 = bias ? bias[c0] : 0.f;
            float b1 = bias ? bias[c0 + 1] : 0.f;
            float v0 = acc[mi][ni][0] + b0;
            float v1 = acc[mi][ni][1] + b1;
            float v2 = acc[mi][ni][2] + b0;
            float v3 = acc[mi][ni][3] + b1;
            if (res) {
                v0 += res[(size_t)r0 * N + c0];
                v1 += res[(size_t)r0 * N + c0 + 1];
                v2 += res[(size_t)(r0 + 8) * N + c0];
                v3 += res[(size_t)(r0 + 8) * N + c0 + 1];
            }
            if (relu) {
                v0 = fmaxf(v0, 0.f); v1 = fmaxf(v1, 0.f);
                v2 = fmaxf(v2, 0.f); v3 = fmaxf(v3, 0.f);
            }
            C[(size_t)r0 * N + c0]           = v0;
            C[(size_t)r0 * N + c0 + 1]       = v1;
            C[(size_t)(r0 + 8) * N + c0]     = v2;
            C[(size_t)(r0 + 8) * N + c0 + 1] = v3;
        }
    }
}

// ---------------- causal flash attention (unchanged) ------------------------
__global__ void __launch_bounds__(64)
attn_kernel(const float* __restrict__ qkv, float* __restrict__ outp) {
    int qt = blockIdx.x;
    int h  = blockIdx.y;
    int b  = blockIdx.z;
    int r  = threadIdx.x;

    __shared__ float ks[64][68];
    __shared__ float vs[64][68];

    int qi = qt * 64 + r;
    const float* qrow = qkv + ((size_t)(b * SEQ + qi)) * QKVCOLS + h * 64;
    float q[64];
    #pragma unroll
    for (int e = 0; e < 64; e++) q[e] = qrow[e];

    float o[64];
    #pragma unroll
    for (int e = 0; e < 64; e++) o[e] = 0.f;
    float m = -1e30f, l = 0.f;

    for (int kt = 0; kt <= qt; kt++) {
        const float* kbase = qkv + ((size_t)(b * SEQ + kt * 64)) * QKVCOLS + NEMBD + h * 64;
        const float* vbase = kbase + NEMBD;
        #pragma unroll 8
        for (int i = 0; i < 64; i++) {
            ks[i][r] = kbase[(size_t)i * QKVCOLS + r];
            vs[i][r] = vbase[(size_t)i * QKVCOLS + r];
        }
        __syncthreads();

        int jmax = (kt == qt) ? r : 63;
        for (int jc = 0; jc < 64; jc += 8) {
            if (jc > jmax) break;
            float sv[8];
            #pragma unroll
            for (int u = 0; u < 8; u++) {
                float sj = 0.f;
                #pragma unroll
                for (int e = 0; e < 64; e += 4) {
                    float4 kk = *(const float4*)&ks[jc + u][e];
                    sj += q[e] * kk.x + q[e + 1] * kk.y + q[e + 2] * kk.z + q[e + 3] * kk.w;
                }
                sv[u] = (jc + u > jmax) ? -1e30f : sj * 0.125f;
            }
            float mt = m;
            #pragma unroll
            for (int u = 0; u < 8; u++) mt = fmaxf(mt, sv[u]);
            float sc = __expf(m - mt);
            m = mt;
            l *= sc;
            float p[8];
            float ps = 0.f;
            #pragma unroll
            for (int u = 0; u < 8; u++) { p[u] = __expf(sv[u] - mt); ps += p[u]; }
            l += ps;
            #pragma unroll
            for (int e = 0; e < 64; e += 4) {
                float ax = o[e] * sc, ay = o[e+1] * sc, az = o[e+2] * sc, aw = o[e+3] * sc;
                #pragma unroll
                for (int u = 0; u < 8; u++) {
                    float4 vv = *(const float4*)&vs[jc + u][e];
                    ax += p[u] * vv.x; ay += p[u] * vv.y;
                    az += p[u] * vv.z; aw += p[u] * vv.w;
                }
                o[e] = ax; o[e+1] = ay; o[e+2] = az; o[e+3] = aw;
            }
        }
        __syncthreads();
    }

    float inv = 1.f / l;
    float* orow = outp + ((size_t)(b * SEQ + qi)) * NEMBD + h * 64;
    #pragma unroll
    for (int e = 0; e < 64; e++) orow[e] = o[e] * inv;
}

// ---------------- launch ----------------------------------------------------
extern "C" void kernel_launch(void* const* d_in, const int* in_sizes, int n_in,
                              void* d_out, int out_size) {
    const float* x      = (const float*)d_in[0];
    const float* wq     = (const float*)d_in[1];
    const float* wk     = (const float*)d_in[2];
    const float* wv     = (const float*)d_in[3];
    const float* w_proj = (const float*)d_in[4];
    const float* b_proj = (const float*)d_in[5];
    const float* w1     = (const float*)d_in[6];
    const float* b1     = (const float*)d_in[7];
    const float* w2     = (const float*)d_in[8];
    const float* b2     = (const float*)d_in[9];
    const float* g1     = (const float*)d_in[10];
    const float* be1    = (const float*)d_in[11];
    const float* g2     = (const float*)d_in[12];
    const float* be2    = (const float*)d_in[13];
    float* out = (float*)d_out;

    float *p_xn1, *p_wqkv, *p_qkv, *p_attn, *p_x2, *p_xn2, *p_h;
    cudaGetSymbolAddress((void**)&p_xn1,  g_xn1);
    cudaGetSymbolAddress((void**)&p_wqkv, g_wqkv);
    cudaGetSymbolAddress((void**)&p_qkv,  g_qkv);
    cudaGetSymbolAddress((void**)&p_attn, g_attn);
    cudaGetSymbolAddress((void**)&p_x2,   g_x2);
    cudaGetSymbolAddress((void**)&p_xn2,  g_xn2);
    cudaGetSymbolAddress((void**)&p_h,    g_h);

    // 1. repack qkv weights
    repack_qkv_kernel<<<(NEMBD * QKVCOLS + 255) / 256, 256>>>(wq, wk, wv, p_wqkv);
    // 2. LN1
    ln_kernel<<<ROWS, 256>>>(x, p_xn1, g1, be1);
    // 3. QKV projection
    tcgemm_kernel<<<dim3(QKVCOLS / 128, ROWS / 128), 256>>>(
        p_xn1, p_wqkv, p_qkv, ROWS, QKVCOLS, NEMBD, nullptr, nullptr, 0);
    // 4. causal attention
    attn_kernel<<<dim3(SEQ / 64, NHEAD, BATCH), 64>>>(p_qkv, p_attn);
    // 5. output projection + bias + residual(xn1)
    tcgemm_kernel<<<dim3(NEMBD / 128, ROWS / 128), 256>>>(
        p_attn, w_proj, p_x2, ROWS, NEMBD, NEMBD, b_proj, p_xn1, 0);
    // 6. LN2
    ln_kernel<<<ROWS, 256>>>(p_x2, p_xn2, g2, be2);
    // 7. FFN up + bias + relu
    tcgemm_kernel<<<dim3(FFDIM / 128, ROWS / 128), 256>>>(
        p_xn2, w1, p_h, ROWS, FFDIM, NEMBD, b1, nullptr, 1);
    // 8. FFN down + bias + residual(xn2) -> out
    tcgemm_kernel<<<dim3(NEMBD / 128, ROWS / 128), 256>>>(
        p_h, w2, out, ROWS, NEMBD, FFDIM, b2, p_xn2, 0);
}

// round 9
// speedup vs baseline: 3.6232x; 1.2440x over previous
#include <cuda_runtime.h>
#include <cuda_bf16.h>
#include <math.h>
#include <stdint.h>

// Problem dims
#define BATCH   8
#define SEQ     1024
#define NEMBD   1024
#define NHEAD   16
#define HSIZE   64
#define FFDIM   4096
#define ROWS    (BATCH * SEQ)          // 8192
#define QKVCOLS (3 * NEMBD)            // 3072

// ---------------- scratch (device globals; no allocation allowed) ----------
__device__ float g_xn1[ROWS * NEMBD];
__device__ float g_wqkv[NEMBD * QKVCOLS];
__device__ float g_qkv[ROWS * QKVCOLS];
__device__ float g_attn[ROWS * NEMBD];
__device__ float g_x2[ROWS * NEMBD];
__device__ float g_xn2[ROWS * NEMBD];
__device__ float g_h[ROWS * FFDIM];

// ---------------- weight repack ---------------------------------------------
__global__ void repack_qkv_kernel(const float* __restrict__ wq,
                                  const float* __restrict__ wk,
                                  const float* __restrict__ wv,
                                  float* __restrict__ W) {
    int idx = blockIdx.x * 256 + threadIdx.x;
    if (idx >= NEMBD * QKVCOLS) return;
    int d = idx / QKVCOLS;
    int j = idx - d * QKVCOLS;
    int sec = j >> 10;
    int within = j & 1023;
    int h = within >> 6;
    int e = within & 63;
    const float* src = (sec == 0) ? wq : (sec == 1) ? wk : wv;
    W[idx] = src[((size_t)h * NEMBD + d) * HSIZE + e];
}

// ---------------- LayerNorm -------------------------------------------------
__global__ void ln_kernel(const float* __restrict__ in, float* __restrict__ out,
                          const float* __restrict__ gamma, const float* __restrict__ beta) {
    int row = blockIdx.x;
    const float4* x4 = (const float4*)(in + (size_t)row * NEMBD);
    int i = threadIdx.x;
    float4 a = x4[i];
    float s  = a.x + a.y + a.z + a.w;
    float s2 = a.x * a.x + a.y * a.y + a.z * a.z + a.w * a.w;

    #pragma unroll
    for (int o = 16; o; o >>= 1) {
        s  += __shfl_xor_sync(0xffffffffu, s, o);
        s2 += __shfl_xor_sync(0xffffffffu, s2, o);
    }
    __shared__ float sh[2][8];
    __shared__ float stats[2];
    int lane = threadIdx.x & 31, wid = threadIdx.x >> 5;
    if (lane == 0) { sh[0][wid] = s; sh[1][wid] = s2; }
    __syncthreads();
    if (threadIdx.x == 0) {
        float ts = 0.f, ts2 = 0.f;
        #pragma unroll
        for (int w = 0; w < 8; w++) { ts += sh[0][w]; ts2 += sh[1][w]; }
        float mu  = ts * (1.f / NEMBD);
        float var = ts2 * (1.f / NEMBD) - mu * mu;
        stats[0] = mu;
        stats[1] = rsqrtf(var + 1e-5f);
    }
    __syncthreads();
    float mu = stats[0], inv = stats[1];
    float4 g = ((const float4*)gamma)[i];
    float4 b = ((const float4*)beta)[i];
    float4 r;
    r.x = (a.x - mu) * inv * g.x + b.x;
    r.y = (a.y - mu) * inv * g.y + b.y;
    r.z = (a.z - mu) * inv * g.z + b.z;
    r.w = (a.w - mu) * inv * g.w + b.w;
    ((float4*)(out + (size_t)row * NEMBD))[i] = r;
}

// ---------------- MMA helpers -----------------------------------------------
__device__ __forceinline__ uint32_t smem_u32(const void* p) {
    return (uint32_t)__cvta_generic_to_shared(p);
}
__device__ __forceinline__ void ldsm_x4(uint32_t* r, uint32_t addr) {
    asm volatile("ldmatrix.sync.aligned.m8n8.x4.shared.b16 {%0,%1,%2,%3}, [%4];"
                 : "=r"(r[0]), "=r"(r[1]), "=r"(r[2]), "=r"(r[3]) : "r"(addr));
}
__device__ __forceinline__ void ldsm_x2(uint32_t* r, uint32_t addr) {
    asm volatile("ldmatrix.sync.aligned.m8n8.x2.shared.b16 {%0,%1}, [%2];"
                 : "=r"(r[0]), "=r"(r[1]) : "r"(addr));
}
__device__ __forceinline__ void ldsm_x2t(uint32_t* r, uint32_t addr) {
    asm volatile("ldmatrix.sync.aligned.m8n8.x2.trans.shared.b16 {%0,%1}, [%2];"
                 : "=r"(r[0]), "=r"(r[1]) : "r"(addr));
}
__device__ __forceinline__ void mma16816(float* c, const uint32_t* a, const uint32_t* b) {
    asm volatile("mma.sync.aligned.m16n8k16.row.col.f32.bf16.bf16.f32 "
                 "{%0,%1,%2,%3}, {%4,%5,%6,%7}, {%8,%9}, {%0,%1,%2,%3};"
                 : "+f"(c[0]), "+f"(c[1]), "+f"(c[2]), "+f"(c[3])
                 : "r"(a[0]), "r"(a[1]), "r"(a[2]), "r"(a[3]),
                   "r"(b[0]), "r"(b[1]));
}
__device__ __forceinline__ uint32_t pack2(__nv_bfloat16 a, __nv_bfloat16 b) {
    return (uint32_t)__bfloat16_as_ushort(a) | ((uint32_t)__bfloat16_as_ushort(b) << 16);
}
__device__ __forceinline__ void store_split(__nv_bfloat16* ph, __nv_bfloat16* pl, float4 v) {
    __nv_bfloat16 hx = __float2bfloat16_rn(v.x);
    __nv_bfloat16 hy = __float2bfloat16_rn(v.y);
    __nv_bfloat16 hz = __float2bfloat16_rn(v.z);
    __nv_bfloat16 hw = __float2bfloat16_rn(v.w);
    __nv_bfloat16 lx = __float2bfloat16_rn(v.x - __bfloat162float(hx));
    __nv_bfloat16 ly = __float2bfloat16_rn(v.y - __bfloat162float(hy));
    __nv_bfloat16 lz = __float2bfloat16_rn(v.z - __bfloat162float(hz));
    __nv_bfloat16 lw = __float2bfloat16_rn(v.w - __bfloat162float(hw));
    *(uint2*)ph = make_uint2(pack2(hx, hy), pack2(hz, hw));
    *(uint2*)pl = make_uint2(pack2(lx, ly), pack2(lz, lw));
}

// fast exp2 for x <= 0 (clamped): magic-number round + deg-5 Taylor in f*ln2
__device__ __forceinline__ float exp2_fast(float x) {
    x = fmaxf(x, -120.f);
    float z = x + 12582912.f;            // 1.5*2^23: round-to-nearest-int
    float i = z - 12582912.f;
    float f = x - i;                      // f in [-0.5, 0.5]
    float y = f * 0.6931471805599453f;
    float p = 0.008333333f;
    p = fmaf(p, y, 0.041666668f);
    p = fmaf(p, y, 0.16666667f);
    p = fmaf(p, y, 0.5f);
    p = fmaf(p, y, 1.0f);
    p = fmaf(p, y, 1.0f);
    int ii = __float_as_int(z) - 0x4B400000;       // signed integer part
    return p * __int_as_float((ii + 127) << 23);
}

// ---------------- tensor-core GEMM (bf16 2-term split) ----------------------
#define APAD 40
#define BPAD 136

__global__ void __launch_bounds__(256)
tcgemm_kernel(const float* __restrict__ A, const float* __restrict__ B,
              float* __restrict__ C, int M, int N, int K,
              const float* __restrict__ bias, const float* __restrict__ res, int relu) {
    __shared__ __nv_bfloat16 As_h[128][APAD];
    __shared__ __nv_bfloat16 As_l[128][APAD];
    __shared__ __nv_bfloat16 Bs_h[32][BPAD];
    __shared__ __nv_bfloat16 Bs_l[32][BPAD];

    int bx = blockIdx.x, by = blockIdx.y;
    int tid = threadIdx.x;
    int lane = tid & 31, warp = tid >> 5;
    int wm = (warp >> 2) * 64;
    int wn = (warp & 3) * 32;

    float acc[4][4][4];
    #pragma unroll
    for (int mi = 0; mi < 4; mi++)
        #pragma unroll
        for (int ni = 0; ni < 4; ni++)
            #pragma unroll
            for (int q = 0; q < 4; q++) acc[mi][ni][q] = 0.f;

    float4 aReg[4], bReg[4];

    #pragma unroll
    for (int i = 0; i < 4; i++) {
        int idx = tid + i * 256;
        int rowA = idx >> 3, c4A = idx & 7;
        aReg[i] = *(const float4*)(A + (size_t)(by * 128 + rowA) * K + c4A * 4);
        int rowB = idx >> 5, c4B = idx & 31;
        bReg[i] = *(const float4*)(B + (size_t)rowB * N + bx * 128 + c4B * 4);
    }

    int ntiles = K / 32;
    for (int t = 0; t < ntiles; t++) {
        #pragma unroll
        for (int i = 0; i < 4; i++) {
            int idx = tid + i * 256;
            int rowA = idx >> 3, c4A = idx & 7;
            store_split(&As_h[rowA][c4A * 4], &As_l[rowA][c4A * 4], aReg[i]);
            int rowB = idx >> 5, c4B = idx & 31;
            store_split(&Bs_h[rowB][c4B * 4], &Bs_l[rowB][c4B * 4], bReg[i]);
        }
        __syncthreads();

        if (t + 1 < ntiles) {
            int k0 = (t + 1) * 32;
            #pragma unroll
            for (int i = 0; i < 4; i++) {
                int idx = tid + i * 256;
                int rowA = idx >> 3, c4A = idx & 7;
                aReg[i] = *(const float4*)(A + (size_t)(by * 128 + rowA) * K + k0 + c4A * 4);
                int rowB = idx >> 5, c4B = idx & 31;
                bReg[i] = *(const float4*)(B + (size_t)(k0 + rowB) * N + bx * 128 + c4B * 4);
            }
        }

        #pragma unroll
        for (int kk = 0; kk < 2; kk++) {
            int kb = kk * 16;
            uint32_t bh[4][2], bl[4][2];
            #pragma unroll
            for (int ni = 0; ni < 4; ni++) {
                ldsm_x2t(bh[ni], smem_u32(&Bs_h[kb + (lane & 15)][wn + ni * 8]));
                ldsm_x2t(bl[ni], smem_u32(&Bs_l[kb + (lane & 15)][wn + ni * 8]));
            }
            #pragma unroll
            for (int mi = 0; mi < 4; mi++) {
                uint32_t ah[4], al[4];
                ldsm_x4(ah, smem_u32(&As_h[wm + mi * 16 + (lane & 15)][kb + (lane >> 4) * 8]));
                ldsm_x4(al, smem_u32(&As_l[wm + mi * 16 + (lane & 15)][kb + (lane >> 4) * 8]));
                #pragma unroll
                for (int ni = 0; ni < 4; ni++) {
                    mma16816(acc[mi][ni], ah, bh[ni]);
                    mma16816(acc[mi][ni], ah, bl[ni]);
                    mma16816(acc[mi][ni], al, bh[ni]);
                }
            }
        }
        __syncthreads();
    }

    int g = lane >> 2, tig = lane & 3;
    #pragma unroll
    for (int mi = 0; mi < 4; mi++) {
        #pragma unroll
        for (int ni = 0; ni < 4; ni++) {
            int r0 = by * 128 + wm + mi * 16 + g;
            int c0 = bx * 128 + wn + ni * 8 + tig * 2;
            float b0 = bias ? bias[c0] : 0.f;
            float b1 = bias ? bias[c0 + 1] : 0.f;
            float v0 = acc[mi][ni][0] + b0;
            float v1 = acc[mi][ni][1] + b1;
            float v2 = acc[mi][ni][2] + b0;
            float v3 = acc[mi][ni][3] + b1;
            if (res) {
                v0 += res[(size_t)r0 * N + c0];
                v1 += res[(size_t)r0 * N + c0 + 1];
                v2 += res[(size_t)(r0 + 8) * N + c0];
                v3 += res[(size_t)(r0 + 8) * N + c0 + 1];
            }
            if (relu) {
                v0 = fmaxf(v0, 0.f); v1 = fmaxf(v1, 0.f);
                v2 = fmaxf(v2, 0.f); v3 = fmaxf(v3, 0.f);
            }
            C[(size_t)r0 * N + c0]           = v0;
            C[(size_t)r0 * N + c0 + 1]       = v1;
            C[(size_t)(r0 + 8) * N + c0]     = v2;
            C[(size_t)(r0 + 8) * N + c0 + 1] = v3;
        }
    }
}

// ---------------- MMA flash attention ---------------------------------------
// Block = 128 thr (4 warps). Br=Bc=64, E=64. Warp w owns q rows [w*16, w*16+16).
// grid (SEQ/64, NHEAD, BATCH). bf16 2-term split for QK^T and PV; fp32 softmax.
#define KPAD 72   // 64 + 8 halves; 144B row stride -> conflict-free ldmatrix

__global__ void __launch_bounds__(128)
attn_mma_kernel(const float* __restrict__ qkv, float* __restrict__ outp) {
    __shared__ __nv_bfloat16 Ks_h[64][KPAD];
    __shared__ __nv_bfloat16 Ks_l[64][KPAD];
    __shared__ __nv_bfloat16 Vs_h[64][KPAD];
    __shared__ __nv_bfloat16 Vs_l[64][KPAD];

    int qt = blockIdx.x;
    int h  = blockIdx.y;
    int b  = blockIdx.z;
    int tid = threadIdx.x;
    int lane = tid & 31, w = tid >> 5;

    const float alpha = 0.125f * 1.4426950408889634f;  // scale * log2(e)

    // ---- stage Q (scaled) into K buffers, pull fragments, then release -----
    {
        const float* qbase = qkv + ((size_t)(b * SEQ + qt * 64)) * QKVCOLS + h * 64;
        #pragma unroll
        for (int i = 0; i < 8; i++) {
            int idx = tid + i * 128;
            int row = idx >> 4, c4 = idx & 15;
            float4 v = *(const float4*)(qbase + (size_t)row * QKVCOLS + c4 * 4);
            v.x *= alpha; v.y *= alpha; v.z *= alpha; v.w *= alpha;
            store_split(&Ks_h[row][c4 * 4], &Ks_l[row][c4 * 4], v);
        }
    }
    __syncthreads();

    uint32_t qa_h[4][4], qa_l[4][4];
    #pragma unroll
    for (int ks = 0; ks < 4; ks++) {
        uint32_t ar = smem_u32(&Ks_h[w * 16 + (lane & 15)][ks * 16 + (lane >> 4) * 8]);
        ldsm_x4(qa_h[ks], ar);
        uint32_t al = smem_u32(&Ks_l[w * 16 + (lane & 15)][ks * 16 + (lane >> 4) * 8]);
        ldsm_x4(qa_l[ks], al);
    }
    __syncthreads();

    float o[8][4];
    #pragma unroll
    for (int ne = 0; ne < 8; ne++)
        #pragma unroll
        for (int q = 0; q < 4; q++) o[ne][q] = 0.f;
    float m0 = -1e30f, m1 = -1e30f, l0 = 0.f, l1 = 0.f;

    int qrow0 = qt * 64 + w * 16 + (lane >> 2);   // rows for c0/c1; +8 for c2/c3

    for (int kt = 0; kt <= qt; kt++) {
        // ---- load K,V tile (fp32 -> split bf16 smem) -----------------------
        const float* kbase = qkv + ((size_t)(b * SEQ + kt * 64)) * QKVCOLS + NEMBD + h * 64;
        const float* vbase = kbase + NEMBD;
        #pragma unroll
        for (int i = 0; i < 8; i++) {
            int idx = tid + i * 128;
            int row = idx >> 4, c4 = idx & 15;
            float4 kv = *(const float4*)(kbase + (size_t)row * QKVCOLS + c4 * 4);
            store_split(&Ks_h[row][c4 * 4], &Ks_l[row][c4 * 4], kv);
            float4 vv = *(const float4*)(vbase + (size_t)row * QKVCOLS + c4 * 4);
            store_split(&Vs_h[row][c4 * 4], &Vs_l[row][c4 * 4], vv);
        }
        __syncthreads();

        // ---- S = (alpha*Q) K^T  (split: qh*kh + qh*kl + ql*kh) -------------
        float s[8][4];
        #pragma unroll
        for (int nt = 0; nt < 8; nt++) {
            s[nt][0] = s[nt][1] = s[nt][2] = s[nt][3] = 0.f;
            #pragma unroll
            for (int ks = 0; ks < 4; ks++) {
                uint32_t kh[2], kl[2];
                uint32_t addr_off = (uint32_t)((nt * 8 + (lane & 7)) * KPAD +
                                               ks * 16 + ((lane >> 3) & 1) * 8);
                ldsm_x2(kh, smem_u32(&Ks_h[0][0]) + addr_off * 2);
                ldsm_x2(kl, smem_u32(&Ks_l[0][0]) + addr_off * 2);
                mma16816(s[nt], qa_h[ks], kh);
                mma16816(s[nt], qa_h[ks], kl);
                mma16816(s[nt], qa_l[ks], kh);
            }
        }

        // ---- causal mask on diagonal tile ----------------------------------
        if (kt == qt) {
            #pragma unroll
            for (int nt = 0; nt < 8; nt++) {
                int key = kt * 64 + nt * 8 + (lane & 3) * 2;
                if (key     > qrow0)     s[nt][0] = -1e30f;
                if (key + 1 > qrow0)     s[nt][1] = -1e30f;
                if (key     > qrow0 + 8) s[nt][2] = -1e30f;
                if (key + 1 > qrow0 + 8) s[nt][3] = -1e30f;
            }
        }

        // ---- online softmax (base-2 domain) --------------------------------
        float mt0 = -1e30f, mt1 = -1e30f;
        #pragma unroll
        for (int nt = 0; nt < 8; nt++) {
            mt0 = fmaxf(mt0, fmaxf(s[nt][0], s[nt][1]));
            mt1 = fmaxf(mt1, fmaxf(s[nt][2], s[nt][3]));
        }
        mt0 = fmaxf(mt0, __shfl_xor_sync(0xffffffffu, mt0, 1));
        mt0 = fmaxf(mt0, __shfl_xor_sync(0xffffffffu, mt0, 2));
        mt1 = fmaxf(mt1, __shfl_xor_sync(0xffffffffu, mt1, 1));
        mt1 = fmaxf(mt1, __shfl_xor_sync(0xffffffffu, mt1, 2));
        float nm0 = fmaxf(m0, mt0);
        float nm1 = fmaxf(m1, mt1);
        float sc0 = exp2_fast(m0 - nm0);
        float sc1 = exp2_fast(m1 - nm1);
        m0 = nm0; m1 = nm1;

        float sum0 = 0.f, sum1 = 0.f;
        #pragma unroll
        for (int nt = 0; nt < 8; nt++) {
            s[nt][0] = exp2_fast(s[nt][0] - m0);
            s[nt][1] = exp2_fast(s[nt][1] - m0);
            s[nt][2] = exp2_fast(s[nt][2] - m1);
            s[nt][3] = exp2_fast(s[nt][3] - m1);
            sum0 += s[nt][0] + s[nt][1];
            sum1 += s[nt][2] + s[nt][3];
        }
        sum0 += __shfl_xor_sync(0xffffffffu, sum0, 1);
        sum0 += __shfl_xor_sync(0xffffffffu, sum0, 2);
        sum1 += __shfl_xor_sync(0xffffffffu, sum1, 1);
        sum1 += __shfl_xor_sync(0xffffffffu, sum1, 2);
        l0 = l0 * sc0 + sum0;
        l1 = l1 * sc1 + sum1;

        #pragma unroll
        for (int ne = 0; ne < 8; ne++) {
            o[ne][0] *= sc0; o[ne][1] *= sc0;
            o[ne][2] *= sc1; o[ne][3] *= sc1;
        }

        // ---- split P into a-frags ------------------------------------------
        uint32_t pa_h[4][4], pa_l[4][4];
        #pragma unroll
        for (int pk = 0; pk < 4; pk++) {
            #pragma unroll
            for (int q = 0; q < 4; q++) {
                float v0 = s[2 * pk + (q >> 1)][(q & 1) ? 2 : 0];
                float v1 = s[2 * pk + (q >> 1)][(q & 1) ? 3 : 1];
                __nv_bfloat16 h0 = __float2bfloat16_rn(v0);
                __nv_bfloat16 h1 = __float2bfloat16_rn(v1);
                pa_h[pk][q] = pack2(h0, h1);
                pa_l[pk][q] = pack2(__float2bfloat16_rn(v0 - __bfloat162float(h0)),
                                    __float2bfloat16_rn(v1 - __bfloat162float(h1)));
            }
        }
        // fix frag index order: a0=(r,k0),a1=(r+8,k0),a2=(r,k8),a3=(r+8,k8)
        // mapping above: q=0 -> tile 2pk cols c0,c1 (row r);   q=1 -> tile 2pk c2,c3 (row r+8)
        //                q=2 -> tile 2pk+1 c0,c1 (r, k+8);     q=3 -> tile 2pk+1 c2,c3 (r+8, k+8)

        // ---- O += P V  (split: ph*vh + ph*vl + pl*vh) ----------------------
        #pragma unroll
        for (int ne = 0; ne < 8; ne++) {
            #pragma unroll
            for (int pk = 0; pk < 4; pk++) {
                uint32_t vh[2], vl[2];
                uint32_t addr_off = (uint32_t)((pk * 16 + (lane & 15)) * KPAD + ne * 8);
                ldsm_x2t(vh, smem_u32(&Vs_h[0][0]) + addr_off * 2);
                ldsm_x2t(vl, smem_u32(&Vs_l[0][0]) + addr_off * 2);
                mma16816(o[ne], pa_h[pk], vh);
                mma16816(o[ne], pa_h[pk], vl);
                mma16816(o[ne], pa_l[pk], vh);
            }
        }
        __syncthreads();
    }

    // ---- normalize + write out --------------------------------------------
    float inv0 = 1.f / l0;
    float inv1 = 1.f / l1;
    float* ob = outp + ((size_t)(b * SEQ + qrow0)) * NEMBD + h * 64 + (lane & 3) * 2;
    #pragma unroll
    for (int ne = 0; ne < 8; ne++) {
        *(float2*)(ob + ne * 8)               = make_float2(o[ne][0] * inv0, o[ne][1] * inv0);
        *(float2*)(ob + 8 * NEMBD + ne * 8)   = make_float2(o[ne][2] * inv1, o[ne][3] * inv1);
    }
}

// ---------------- launch ----------------------------------------------------
extern "C" void kernel_launch(void* const* d_in, const int* in_sizes, int n_in,
                              void* d_out, int out_size) {
    const float* x      = (const float*)d_in[0];
    const float* wq     = (const float*)d_in[1];
    const float* wk     = (const float*)d_in[2];
    const float* wv     = (const float*)d_in[3];
    const float* w_proj = (const float*)d_in[4];
    const float* b_proj = (const float*)d_in[5];
    const float* w1     = (const float*)d_in[6];
    const float* b1     = (const float*)d_in[7];
    const float* w2     = (const float*)d_in[8];
    const float* b2     = (const float*)d_in[9];
    const float* g1     = (const float*)d_in[10];
    const float* be1    = (const float*)d_in[11];
    const float* g2     = (const float*)d_in[12];
    const float* be2    = (const float*)d_in[13];
    float* out = (float*)d_out;

    float *p_xn1, *p_wqkv, *p_qkv, *p_attn, *p_x2, *p_xn2, *p_h;
    cudaGetSymbolAddress((void**)&p_xn1,  g_xn1);
    cudaGetSymbolAddress((void**)&p_wqkv, g_wqkv);
    cudaGetSymbolAddress((void**)&p_qkv,  g_qkv);
    cudaGetSymbolAddress((void**)&p_attn, g_attn);
    cudaGetSymbolAddress((void**)&p_x2,   g_x2);
    cudaGetSymbolAddress((void**)&p_xn2,  g_xn2);
    cudaGetSymbolAddress((void**)&p_h,    g_h);

    repack_qkv_kernel<<<(NEMBD * QKVCOLS + 255) / 256, 256>>>(wq, wk, wv, p_wqkv);
    ln_kernel<<<ROWS, 256>>>(x, p_xn1, g1, be1);
    tcgemm_kernel<<<dim3(QKVCOLS / 128, ROWS / 128), 256>>>(
        p_xn1, p_wqkv, p_qkv, ROWS, QKVCOLS, NEMBD, nullptr, nullptr, 0);
    attn_mma_kernel<<<dim3(SEQ / 64, NHEAD, BATCH), 128>>>(p_qkv, p_attn);
    tcgemm_kernel<<<dim3(NEMBD / 128, ROWS / 128), 256>>>(
        p_attn, w_proj, p_x2, ROWS, NEMBD, NEMBD, b_proj, p_xn1, 0);
    ln_kernel<<<ROWS, 256>>>(p_x2, p_xn2, g2, be2);
    tcgemm_kernel<<<dim3(FFDIM / 128, ROWS / 128), 256>>>(
        p_xn2, w1, p_h, ROWS, FFDIM, NEMBD, b1, nullptr, 1);
    tcgemm_kernel<<<dim3(NEMBD / 128, ROWS / 128), 256>>>(
        p_h, w2, out, ROWS, NEMBD, FFDIM, b2, p_xn2, 0);
}

// round 12
// speedup vs baseline: 4.8060x; 1.3265x over previous
#include <cuda_runtime.h>
#include <cuda_bf16.h>
#include <math.h>
#include <stdint.h>

// Problem dims
#define BATCH   8
#define SEQ     1024
#define NEMBD   1024
#define NHEAD   16
#define HSIZE   64
#define FFDIM   4096
#define ROWS    (BATCH * SEQ)          // 8192
#define QKVCOLS (3 * NEMBD)            // 3072

typedef __nv_bfloat16 bf16;

// ---------------- scratch (device globals; no allocation allowed) ----------
__device__ float g_xn1 [ROWS * NEMBD];
__device__ bf16  g_xn1h[ROWS * NEMBD];
__device__ bf16  g_xn1l[ROWS * NEMBD];
__device__ bf16  g_wqkvh[NEMBD * QKVCOLS];
__device__ bf16  g_wqkvl[NEMBD * QKVCOLS];
__device__ bf16  g_wprojh[NEMBD * NEMBD];
__device__ bf16  g_wprojl[NEMBD * NEMBD];
__device__ bf16  g_w1h[NEMBD * FFDIM];
__device__ bf16  g_w1l[NEMBD * FFDIM];
__device__ bf16  g_w2h[FFDIM * NEMBD];
__device__ bf16  g_w2l[FFDIM * NEMBD];
__device__ bf16  g_qkvh[ROWS * QKVCOLS];
__device__ bf16  g_qkvl[ROWS * QKVCOLS];
__device__ bf16  g_attnh[ROWS * NEMBD];
__device__ bf16  g_attnl[ROWS * NEMBD];
__device__ float g_x2  [ROWS * NEMBD];
__device__ float g_xn2 [ROWS * NEMBD];
__device__ bf16  g_xn2h[ROWS * NEMBD];
__device__ bf16  g_xn2l[ROWS * NEMBD];
__device__ bf16  g_hh[ROWS * FFDIM];
__device__ bf16  g_hl[ROWS * FFDIM];

// ---------------- helpers ---------------------------------------------------
__device__ __forceinline__ uint32_t smem_u32(const void* p) {
    return (uint32_t)__cvta_generic_to_shared(p);
}
__device__ __forceinline__ void cpa16(uint32_t dst, const void* src) {
    asm volatile("cp.async.cg.shared.global [%0], [%1], 16;" :: "r"(dst), "l"(src));
}
#define CP_COMMIT() asm volatile("cp.async.commit_group;")
#define CP_WAIT(n)  asm volatile("cp.async.wait_group %0;" :: "n"(n))

__device__ __forceinline__ void ldsm_x4(uint32_t* r, uint32_t addr) {
    asm volatile("ldmatrix.sync.aligned.m8n8.x4.shared.b16 {%0,%1,%2,%3}, [%4];"
                 : "=r"(r[0]), "=r"(r[1]), "=r"(r[2]), "=r"(r[3]) : "r"(addr));
}
__device__ __forceinline__ void ldsm_x2(uint32_t* r, uint32_t addr) {
    asm volatile("ldmatrix.sync.aligned.m8n8.x2.shared.b16 {%0,%1}, [%2];"
                 : "=r"(r[0]), "=r"(r[1]) : "r"(addr));
}
__device__ __forceinline__ void ldsm_x2t(uint32_t* r, uint32_t addr) {
    asm volatile("ldmatrix.sync.aligned.m8n8.x2.trans.shared.b16 {%0,%1}, [%2];"
                 : "=r"(r[0]), "=r"(r[1]) : "r"(addr));
}
__device__ __forceinline__ void mma16816(float* c, const uint32_t* a, const uint32_t* b) {
    asm volatile("mma.sync.aligned.m16n8k16.row.col.f32.bf16.bf16.f32 "
                 "{%0,%1,%2,%3}, {%4,%5,%6,%7}, {%8,%9}, {%0,%1,%2,%3};"
                 : "+f"(c[0]), "+f"(c[1]), "+f"(c[2]), "+f"(c[3])
                 : "r"(a[0]), "r"(a[1]), "r"(a[2]), "r"(a[3]),
                   "r"(b[0]), "r"(b[1]));
}
__device__ __forceinline__ uint32_t pack2(bf16 a, bf16 b) {
    return (uint32_t)__bfloat16_as_ushort(a) | ((uint32_t)__bfloat16_as_ushort(b) << 16);
}
__device__ __forceinline__ void store_split(bf16* ph, bf16* pl, float4 v) {
    bf16 hx = __float2bfloat16_rn(v.x);
    bf16 hy = __float2bfloat16_rn(v.y);
    bf16 hz = __float2bfloat16_rn(v.z);
    bf16 hw = __float2bfloat16_rn(v.w);
    bf16 lx = __float2bfloat16_rn(v.x - __bfloat162float(hx));
    bf16 ly = __float2bfloat16_rn(v.y - __bfloat162float(hy));
    bf16 lz = __float2bfloat16_rn(v.z - __bfloat162float(hz));
    bf16 lw = __float2bfloat16_rn(v.w - __bfloat162float(hw));
    *(uint2*)ph = make_uint2(pack2(hx, hy), pack2(hz, hw));
    *(uint2*)pl = make_uint2(pack2(lx, ly), pack2(lz, lw));
}

// fast exp2 for x <= 0 (clamped)
__device__ __forceinline__ float exp2_fast(float x) {
    x = fmaxf(x, -120.f);
    float z = x + 12582912.f;
    float i = z - 12582912.f;
    float f = x - i;
    float y = f * 0.6931471805599453f;
    float p = 0.008333333f;
    p = fmaf(p, y, 0.041666668f);
    p = fmaf(p, y, 0.16666667f);
    p = fmaf(p, y, 0.5f);
    p = fmaf(p, y, 1.0f);
    p = fmaf(p, y, 1.0f);
    int ii = __float_as_int(z) - 0x4B400000;
    return p * __int_as_float((ii + 127) << 23);
}

// ---------------- weight split kernels --------------------------------------
__global__ void repack_split_kernel(const float* __restrict__ wq,
                                    const float* __restrict__ wk,
                                    const float* __restrict__ wv,
                                    bf16* __restrict__ Wh, bf16* __restrict__ Wl) {
    int i = blockIdx.x * 256 + threadIdx.x;          // 4-element groups
    if (i >= NEMBD * QKVCOLS / 4) return;
    int d = (i * 4) / QKVCOLS;
    int j = (i * 4) - d * QKVCOLS;
    int sec = j >> 10;
    int within = j & 1023;
    int h = within >> 6;
    int e = within & 63;
    const float* src = (sec == 0) ? wq : (sec == 1) ? wk : wv;
    float4 v = *(const float4*)(src + ((size_t)h * NEMBD + d) * HSIZE + e);
    store_split(Wh + (size_t)d * QKVCOLS + j, Wl + (size_t)d * QKVCOLS + j, v);
}

__global__ void split_kernel(const float* __restrict__ src,
                             bf16* __restrict__ dh, bf16* __restrict__ dl, int n4) {
    int i = blockIdx.x * 256 + threadIdx.x;
    if (i >= n4) return;
    float4 v = ((const float4*)src)[i];
    store_split(dh + (size_t)i * 4, dl + (size_t)i * 4, v);
}

// ---------------- LayerNorm (fp32 + split out) ------------------------------
__global__ void ln_kernel(const float* __restrict__ in, float* __restrict__ outf,
                          bf16* __restrict__ outh, bf16* __restrict__ outl,
                          const float* __restrict__ gamma, const float* __restrict__ beta) {
    int row = blockIdx.x;
    const float4* x4 = (const float4*)(in + (size_t)row * NEMBD);
    int i = threadIdx.x;
    float4 a = x4[i];
    float s  = a.x + a.y + a.z + a.w;
    float s2 = a.x * a.x + a.y * a.y + a.z * a.z + a.w * a.w;

    #pragma unroll
    for (int o = 16; o; o >>= 1) {
        s  += __shfl_xor_sync(0xffffffffu, s, o);
        s2 += __shfl_xor_sync(0xffffffffu, s2, o);
    }
    __shared__ float sh[2][8];
    __shared__ float stats[2];
    int lane = threadIdx.x & 31, wid = threadIdx.x >> 5;
    if (lane == 0) { sh[0][wid] = s; sh[1][wid] = s2; }
    __syncthreads();
    if (threadIdx.x == 0) {
        float ts = 0.f, ts2 = 0.f;
        #pragma unroll
        for (int w = 0; w < 8; w++) { ts += sh[0][w]; ts2 += sh[1][w]; }
        float mu  = ts * (1.f / NEMBD);
        float var = ts2 * (1.f / NEMBD) - mu * mu;
        stats[0] = mu;
        stats[1] = rsqrtf(var + 1e-5f);
    }
    __syncthreads();
    float mu = stats[0], inv = stats[1];
    float4 g = ((const float4*)gamma)[i];
    float4 b = ((const float4*)beta)[i];
    float4 r;
    r.x = (a.x - mu) * inv * g.x + b.x;
    r.y = (a.y - mu) * inv * g.y + b.y;
    r.z = (a.z - mu) * inv * g.z + b.z;
    r.w = (a.w - mu) * inv * g.w + b.w;
    ((float4*)(outf + (size_t)row * NEMBD))[i] = r;
    store_split(outh + (size_t)row * NEMBD + i * 4,
                outl + (size_t)row * NEMBD + i * 4, r);
}

// ---------------- cp.async double-buffered split-bf16 GEMM ------------------
// A_h/A_l [M,K] bf16 row-major, B_h/B_l [K,N] bf16 row-major.
// Tile 128x128, kstep 32, 2 stages dynamic smem.
// Stage layout: As_h(128x40) As_l Bs_h(32x136) Bs_l
#define STG_BYTES 37888
#define GEMM_SMEM (2 * STG_BYTES)

__device__ __forceinline__ void gemm_issue(
    char* stbase,
    const bf16* __restrict__ Ah, const bf16* __restrict__ Al,
    const bf16* __restrict__ Bh, const bf16* __restrict__ Bl,
    int by, int bx, int k0, int K, int N, int tid)
{
    bf16* sAh = (bf16*)(stbase);
    bf16* sAl = (bf16*)(stbase + 10240);
    bf16* sBh = (bf16*)(stbase + 20480);
    bf16* sBl = (bf16*)(stbase + 29184);
    #pragma unroll
    for (int i = 0; i < 2; i++) {
        int idx = tid + i * 256;
        int rowA = idx >> 2, ccA = (idx & 3) * 8;
        size_t ga = (size_t)(by * 128 + rowA) * K + k0 + ccA;
        cpa16(smem_u32(sAh + rowA * 40 + ccA), Ah + ga);
        cpa16(smem_u32(sAl + rowA * 40 + ccA), Al + ga);
        int rowB = idx >> 4, ccB = (idx & 15) * 8;
        size_t gb = (size_t)(k0 + rowB) * N + bx * 128 + ccB;
        cpa16(smem_u32(sBh + rowB * 136 + ccB), Bh + gb);
        cpa16(smem_u32(sBl + rowB * 136 + ccB), Bl + gb);
    }
    CP_COMMIT();
}

__global__ void __launch_bounds__(256)
tcgemm2_kernel(const bf16* __restrict__ Ah, const bf16* __restrict__ Al,
               const bf16* __restrict__ Bh, const bf16* __restrict__ Bl,
               float* __restrict__ Cf, bf16* __restrict__ Ch, bf16* __restrict__ Cl,
               int M, int N, int K,
               const float* __restrict__ bias, const float* __restrict__ res, int relu) {
    extern __shared__ __align__(16) char smraw[];

    int bx = blockIdx.x, by = blockIdx.y;
    int tid = threadIdx.x;
    int lane = tid & 31, warp = tid >> 5;
    int wm = (warp >> 2) * 64;
    int wn = (warp & 3) * 32;

    float acc[4][4][4];
    #pragma unroll
    for (int mi = 0; mi < 4; mi++)
        #pragma unroll
        for (int ni = 0; ni < 4; ni++)
            #pragma unroll
            for (int q = 0; q < 4; q++) acc[mi][ni][q] = 0.f;

    int nt = K / 32;
    gemm_issue(smraw, Ah, Al, Bh, Bl, by, bx, 0, K, N, tid);

    for (int t = 0; t < nt; t++) {
        if (t + 1 < nt) {
            gemm_issue(smraw + ((t + 1) & 1) * STG_BYTES, Ah, Al, Bh, Bl,
                       by, bx, (t + 1) * 32, K, N, tid);
            CP_WAIT(1);
        } else {
            CP_WAIT(0);
        }
        __syncthreads();

        char* st = smraw + (t & 1) * STG_BYTES;
        bf16* sAh = (bf16*)(st);
        bf16* sAl = (bf16*)(st + 10240);
        bf16* sBh = (bf16*)(st + 20480);
        bf16* sBl = (bf16*)(st + 29184);

        #pragma unroll
        for (int kk = 0; kk < 2; kk++) {
            int kb = kk * 16;
            uint32_t bh[4][2], bl[4][2];
            #pragma unroll
            for (int ni = 0; ni < 4; ni++) {
                int boff = (kb + (lane & 15)) * 136 + wn + ni * 8;
                ldsm_x2t(bh[ni], smem_u32(sBh + boff));
                ldsm_x2t(bl[ni], smem_u32(sBl + boff));
            }
            #pragma unroll
            for (int mi = 0; mi < 4; mi++) {
                uint32_t ah[4], al[4];
                int aoff = (wm + mi * 16 + (lane & 15)) * 40 + kb + (lane >> 4) * 8;
                ldsm_x4(ah, smem_u32(sAh + aoff));
                ldsm_x4(al, smem_u32(sAl + aoff));
                #pragma unroll
                for (int ni = 0; ni < 4; ni++) {
                    mma16816(acc[mi][ni], ah, bh[ni]);
                    mma16816(acc[mi][ni], ah, bl[ni]);
                    mma16816(acc[mi][ni], al, bh[ni]);
                }
            }
        }
        __syncthreads();
    }

    // epilogue
    int g = lane >> 2, tig = lane & 3;
    #pragma unroll
    for (int mi = 0; mi < 4; mi++) {
        #pragma unroll
        for (int ni = 0; ni < 4; ni++) {
            int r0 = by * 128 + wm + mi * 16 + g;
            int c0 = bx * 128 + wn + ni * 8 + tig * 2;
            float b0 = bias ? bias[c0] : 0.f;
            float b1 = bias ? bias[c0 + 1] : 0.f;
            float v0 = acc[mi][ni][0] + b0;
            float v1 = acc[mi][ni][1] + b1;
            float v2 = acc[mi][ni][2] + b0;
            float v3 = acc[mi][ni][3] + b1;
            if (res) {
                v0 += res[(size_t)r0 * N + c0];
                v1 += res[(size_t)r0 * N + c0 + 1];
                v2 += res[(size_t)(r0 + 8) * N + c0];
                v3 += res[(size_t)(r0 + 8) * N + c0 + 1];
            }
            if (relu) {
                v0 = fmaxf(v0, 0.f); v1 = fmaxf(v1, 0.f);
                v2 = fmaxf(v2, 0.f); v3 = fmaxf(v3, 0.f);
            }
            if (Ch) {
                bf16 h0 = __float2bfloat16_rn(v0), h1 = __float2bfloat16_rn(v1);
                bf16 h2 = __float2bfloat16_rn(v2), h3 = __float2bfloat16_rn(v3);
                *(uint32_t*)&Ch[(size_t)r0 * N + c0]       = pack2(h0, h1);
                *(uint32_t*)&Ch[(size_t)(r0 + 8) * N + c0] = pack2(h2, h3);
                *(uint32_t*)&Cl[(size_t)r0 * N + c0] =
                    pack2(__float2bfloat16_rn(v0 - __bfloat162float(h0)),
                          __float2bfloat16_rn(v1 - __bfloat162float(h1)));
                *(uint32_t*)&Cl[(size_t)(r0 + 8) * N + c0] =
                    pack2(__float2bfloat16_rn(v2 - __bfloat162float(h2)),
                          __float2bfloat16_rn(v3 - __bfloat162float(h3)));
            } else {
                Cf[(size_t)r0 * N + c0]           = v0;
                Cf[(size_t)r0 * N + c0 + 1]       = v1;
                Cf[(size_t)(r0 + 8) * N + c0]     = v2;
                Cf[(size_t)(r0 + 8) * N + c0 + 1] = v3;
            }
        }
    }
}

// ---------------- MMA flash attention (pre-split qkv in, split out) ---------
#define KPAD 72

__global__ void __launch_bounds__(128)
attn_mma2_kernel(const bf16* __restrict__ qh, const bf16* __restrict__ ql,
                 bf16* __restrict__ oh, bf16* __restrict__ ol) {
    __shared__ bf16 Ks_h[64][KPAD];
    __shared__ bf16 Ks_l[64][KPAD];
    __shared__ bf16 Vs_h[64][KPAD];
    __shared__ bf16 Vs_l[64][KPAD];

    int qt = blockIdx.x;
    int h  = blockIdx.y;
    int b  = blockIdx.z;
    int tid = threadIdx.x;
    int lane = tid & 31, w = tid >> 5;

    const float alpha = 0.125f * 1.4426950408889634f;  // scale * log2(e)

    // ---- stage Q into K buffers (plain copies), pull fragments -------------
    {
        const bf16* qbh = qh + ((size_t)(b * SEQ + qt * 64)) * QKVCOLS + h * 64;
        const bf16* qbl = ql + ((size_t)(b * SEQ + qt * 64)) * QKVCOLS + h * 64;
        #pragma unroll
        for (int i = 0; i < 4; i++) {
            int idx = tid + i * 128;
            int row = idx >> 3, cc = (idx & 7) * 8;
            *(uint4*)&Ks_h[row][cc] = *(const uint4*)(qbh + (size_t)row * QKVCOLS + cc);
            *(uint4*)&Ks_l[row][cc] = *(const uint4*)(qbl + (size_t)row * QKVCOLS + cc);
        }
    }
    __syncthreads();

    uint32_t qa_h[4][4], qa_l[4][4];
    #pragma unroll
    for (int ks = 0; ks < 4; ks++) {
        ldsm_x4(qa_h[ks], smem_u32(&Ks_h[w * 16 + (lane & 15)][ks * 16 + (lane >> 4) * 8]));
        ldsm_x4(qa_l[ks], smem_u32(&Ks_l[w * 16 + (lane & 15)][ks * 16 + (lane >> 4) * 8]));
    }
    __syncthreads();

    float o[8][4];
    #pragma unroll
    for (int ne = 0; ne < 8; ne++)
        #pragma unroll
        for (int q = 0; q < 4; q++) o[ne][q] = 0.f;
    float m0 = -1e30f, m1 = -1e30f, l0 = 0.f, l1 = 0.f;

    int qrow0 = qt * 64 + w * 16 + (lane >> 2);

    for (int kt = 0; kt <= qt; kt++) {
        // ---- cp.async K,V tiles (split bf16, no conversion) ----------------
        {
            size_t rb = (size_t)(b * SEQ + kt * 64);
            #pragma unroll
            for (int i = 0; i < 4; i++) {
                int idx = tid + i * 128;
                int row = idx >> 3, cc = (idx & 7) * 8;
                size_t gk = (rb + row) * QKVCOLS + NEMBD + h * 64 + cc;
                size_t gv = gk + NEMBD;
                cpa16(smem_u32(&Ks_h[row][cc]), qh + gk);
                cpa16(smem_u32(&Ks_l[row][cc]), ql + gk);
                cpa16(smem_u32(&Vs_h[row][cc]), qh + gv);
                cpa16(smem_u32(&Vs_l[row][cc]), ql + gv);
            }
            CP_COMMIT();
            CP_WAIT(0);
        }
        __syncthreads();

        // ---- S = Q K^T (raw, alpha folded into softmax) --------------------
        float s[8][4];
        #pragma unroll
        for (int nt = 0; nt < 8; nt++) {
            s[nt][0] = s[nt][1] = s[nt][2] = s[nt][3] = 0.f;
            #pragma unroll
            for (int ks = 0; ks < 4; ks++) {
                uint32_t kh[2], kl[2];
                uint32_t addr_off = (uint32_t)((nt * 8 + (lane & 7)) * KPAD +
                                               ks * 16 + ((lane >> 3) & 1) * 8);
                ldsm_x2(kh, smem_u32(&Ks_h[0][0]) + addr_off * 2);
                ldsm_x2(kl, smem_u32(&Ks_l[0][0]) + addr_off * 2);
                mma16816(s[nt], qa_h[ks], kh);
                mma16816(s[nt], qa_h[ks], kl);
                mma16816(s[nt], qa_l[ks], kh);
            }
        }

        // ---- causal mask ----------------------------------------------------
        if (kt == qt) {
            #pragma unroll
            for (int nt = 0; nt < 8; nt++) {
                int key = kt * 64 + nt * 8 + (lane & 3) * 2;
                if (key     > qrow0)     s[nt][0] = -1e30f;
                if (key + 1 > qrow0)     s[nt][1] = -1e30f;
                if (key     > qrow0 + 8) s[nt][2] = -1e30f;
                if (key + 1 > qrow0 + 8) s[nt][3] = -1e30f;
            }
        }

        // ---- online softmax (raw max, alpha applied in exponent) -----------
        float mt0 = -1e30f, mt1 = -1e30f;
        #pragma unroll
        for (int nt = 0; nt < 8; nt++) {
            mt0 = fmaxf(mt0, fmaxf(s[nt][0], s[nt][1]));
            mt1 = fmaxf(mt1, fmaxf(s[nt][2], s[nt][3]));
        }
        mt0 = fmaxf(mt0, __shfl_xor_sync(0xffffffffu, mt0, 1));
        mt0 = fmaxf(mt0, __shfl_xor_sync(0xffffffffu, mt0, 2));
        mt1 = fmaxf(mt1, __shfl_xor_sync(0xffffffffu, mt1, 1));
        mt1 = fmaxf(mt1, __shfl_xor_sync(0xffffffffu, mt1, 2));
        float nm0 = fmaxf(m0, mt0);
        float nm1 = fmaxf(m1, mt1);
        float sc0 = exp2_fast(alpha * (m0 - nm0));
        float sc1 = exp2_fast(alpha * (m1 - nm1));
        m0 = nm0; m1 = nm1;
        float am0 = alpha * m0, am1 = alpha * m1;

        float sum0 = 0.f, sum1 = 0.f;
        #pragma unroll
        for (int nt = 0; nt < 8; nt++) {
            s[nt][0] = exp2_fast(fmaf(alpha, s[nt][0], -am0));
            s[nt][1] = exp2_fast(fmaf(alpha, s[nt][1], -am0));
            s[nt][2] = exp2_fast(fmaf(alpha, s[nt][2], -am1));
            s[nt][3] = exp2_fast(fmaf(alpha, s[nt][3], -am1));
            sum0 += s[nt][0] + s[nt][1];
            sum1 += s[nt][2] + s[nt][3];
        }
        sum0 += __shfl_xor_sync(0xffffffffu, sum0, 1);
        sum0 += __shfl_xor_sync(0xffffffffu, sum0, 2);
        sum1 += __shfl_xor_sync(0xffffffffu, sum1, 1);
        sum1 += __shfl_xor_sync(0xffffffffu, sum1, 2);
        l0 = l0 * sc0 + sum0;
        l1 = l1 * sc1 + sum1;

        #pragma unroll
        for (int ne = 0; ne < 8; ne++) {
            o[ne][0] *= sc0; o[ne][1] *= sc0;
            o[ne][2] *= sc1; o[ne][3] *= sc1;
        }

        // ---- split P into a-frags ------------------------------------------
        uint32_t pa_h[4][4], pa_l[4][4];
        #pragma unroll
        for (int pk = 0; pk < 4; pk++) {
            #pragma unroll
            for (int q = 0; q < 4; q++) {
                float v0 = s[2 * pk + (q >> 1)][(q & 1) ? 2 : 0];
                float v1 = s[2 * pk + (q >> 1)][(q & 1) ? 3 : 1];
                bf16 h0 = __float2bfloat16_rn(v0);
                bf16 h1 = __float2bfloat16_rn(v1);
                pa_h[pk][q] = pack2(h0, h1);
                pa_l[pk][q] = pack2(__float2bfloat16_rn(v0 - __bfloat162float(h0)),
                                    __float2bfloat16_rn(v1 - __bfloat162float(h1)));
            }
        }

        // ---- O += P V -------------------------------------------------------
        #pragma unroll
        for (int ne = 0; ne < 8; ne++) {
            #pragma unroll
            for (int pk = 0; pk < 4; pk++) {
                uint32_t vh[2], vl[2];
                uint32_t addr_off = (uint32_t)((pk * 16 + (lane & 15)) * KPAD + ne * 8);
                ldsm_x2t(vh, smem_u32(&Vs_h[0][0]) + addr_off * 2);
                ldsm_x2t(vl, smem_u32(&Vs_l[0][0]) + addr_off * 2);
                mma16816(o[ne], pa_h[pk], vh);
                mma16816(o[ne], pa_h[pk], vl);
                mma16816(o[ne], pa_l[pk], vh);
            }
        }
        __syncthreads();
    }

    // ---- normalize + split write -------------------------------------------
    float inv0 = 1.f / l0;
    float inv1 = 1.f / l1;
    size_t r0 = (size_t)(b * SEQ + qrow0);
    int colbase = h * 64 + (lane & 3) * 2;
    #pragma unroll
    for (int ne = 0; ne < 8; ne++) {
        int col = colbase + ne * 8;
        float v0 = o[ne][0] * inv0, v1 = o[ne][1] * inv0;
        float v2 = o[ne][2] * inv1, v3 = o[ne][3] * inv1;
        bf16 h0 = __float2bfloat16_rn(v0), h1 = __float2bfloat16_rn(v1);
        bf16 h2 = __float2bfloat16_rn(v2), h3 = __float2bfloat16_rn(v3);
        *(uint32_t*)&oh[r0 * NEMBD + col]       = pack2(h0, h1);
        *(uint32_t*)&oh[(r0 + 8) * NEMBD + col] = pack2(h2, h3);
        *(uint32_t*)&ol[r0 * NEMBD + col] =
            pack2(__float2bfloat16_rn(v0 - __bfloat162float(h0)),
                  __float2bfloat16_rn(v1 - __bfloat162float(h1)));
        *(uint32_t*)&ol[(r0 + 8) * NEMBD + col] =
            pack2(__float2bfloat16_rn(v2 - __bfloat162float(h2)),
                  __float2bfloat16_rn(v3 - __bfloat162float(h3)));
    }
}

// ---------------- launch ----------------------------------------------------
extern "C" void kernel_launch(void* const* d_in, const int* in_sizes, int n_in,
                              void* d_out, int out_size) {
    const float* x      = (const float*)d_in[0];
    const float* wq     = (const float*)d_in[1];
    const float* wk     = (const float*)d_in[2];
    const float* wv     = (const float*)d_in[3];
    const float* w_proj = (const float*)d_in[4];
    const float* b_proj = (const float*)d_in[5];
    const float* w1     = (const float*)d_in[6];
    const float* b1     = (const float*)d_in[7];
    const float* w2     = (const float*)d_in[8];
    const float* b2     = (const float*)d_in[9];
    const float* g1     = (const float*)d_in[10];
    const float* be1    = (const float*)d_in[11];
    const float* g2     = (const float*)d_in[12];
    const float* be2    = (const float*)d_in[13];
    float* out = (float*)d_out;

    float *p_xn1, *p_x2, *p_xn2;
    bf16 *p_xn1h, *p_xn1l, *p_wqkvh, *p_wqkvl, *p_wprojh, *p_wprojl;
    bf16 *p_w1h, *p_w1l, *p_w2h, *p_w2l, *p_qkvh, *p_qkvl;
    bf16 *p_attnh, *p_attnl, *p_xn2h, *p_xn2l, *p_hh, *p_hl;
    cudaGetSymbolAddress((void**)&p_xn1,   g_xn1);
    cudaGetSymbolAddress((void**)&p_xn1h,  g_xn1h);
    cudaGetSymbolAddress((void**)&p_xn1l,  g_xn1l);
    cudaGetSymbolAddress((void**)&p_wqkvh, g_wqkvh);
    cudaGetSymbolAddress((void**)&p_wqkvl, g_wqkvl);
    cudaGetSymbolAddress((void**)&p_wprojh, g_wprojh);
    cudaGetSymbolAddress((void**)&p_wprojl, g_wprojl);
    cudaGetSymbolAddress((void**)&p_w1h,   g_w1h);
    cudaGetSymbolAddress((void**)&p_w1l,   g_w1l);
    cudaGetSymbolAddress((void**)&p_w2h,   g_w2h);
    cudaGetSymbolAddress((void**)&p_w2l,   g_w2l);
    cudaGetSymbolAddress((void**)&p_qkvh,  g_qkvh);
    cudaGetSymbolAddress((void**)&p_qkvl,  g_qkvl);
    cudaGetSymbolAddress((void**)&p_attnh, g_attnh);
    cudaGetSymbolAddress((void**)&p_attnl, g_attnl);
    cudaGetSymbolAddress((void**)&p_x2,    g_x2);
    cudaGetSymbolAddress((void**)&p_xn2,   g_xn2);
    cudaGetSymbolAddress((void**)&p_xn2h,  g_xn2h);
    cudaGetSymbolAddress((void**)&p_xn2l,  g_xn2l);
    cudaGetSymbolAddress((void**)&p_hh,    g_hh);
    cudaGetSymbolAddress((void**)&p_hl,    g_hl);

    cudaFuncSetAttribute(tcgemm2_kernel,
                         cudaFuncAttributeMaxDynamicSharedMemorySize, GEMM_SMEM);

    // weights -> split bf16 (once per launch)
    repack_split_kernel<<<(NEMBD * QKVCOLS / 4 + 255) / 256, 256>>>(wq, wk, wv, p_wqkvh, p_wqkvl);
    split_kernel<<<(NEMBD * NEMBD / 4 + 255) / 256, 256>>>(w_proj, p_wprojh, p_wprojl, NEMBD * NEMBD / 4);
    split_kernel<<<(NEMBD * FFDIM / 4 + 255) / 256, 256>>>(w1, p_w1h, p_w1l, NEMBD * FFDIM / 4);
    split_kernel<<<(FFDIM * NEMBD / 4 + 255) / 256, 256>>>(w2, p_w2h, p_w2l, FFDIM * NEMBD / 4);

    // LN1 (fp32 + split)
    ln_kernel<<<ROWS, 256>>>(x, p_xn1, p_xn1h, p_xn1l, g1, be1);

    // QKV projection -> split qkv
    tcgemm2_kernel<<<dim3(QKVCOLS / 128, ROWS / 128), 256, GEMM_SMEM>>>(
        p_xn1h, p_xn1l, p_wqkvh, p_wqkvl,
        nullptr, p_qkvh, p_qkvl, ROWS, QKVCOLS, NEMBD, nullptr, nullptr, 0);

    // attention -> split attn
    attn_mma2_kernel<<<dim3(SEQ / 64, NHEAD, BATCH), 128>>>(p_qkvh, p_qkvl, p_attnh, p_attnl);

    // output projection + bias + residual(xn1 fp32) -> x2 fp32
    tcgemm2_kernel<<<dim3(NEMBD / 128, ROWS / 128), 256, GEMM_SMEM>>>(
        p_attnh, p_attnl, p_wprojh, p_wprojl,
        p_x2, nullptr, nullptr, ROWS, NEMBD, NEMBD, b_proj, p_xn1, 0);

    // LN2 (fp32 + split)
    ln_kernel<<<ROWS, 256>>>(p_x2, p_xn2, p_xn2h, p_xn2l, g2, be2);

    // FFN up + bias + relu -> split h
    tcgemm2_kernel<<<dim3(FFDIM / 128, ROWS / 128), 256, GEMM_SMEM>>>(
        p_xn2h, p_xn2l, p_w1h, p_w1l,
        nullptr, p_hh, p_hl, ROWS, FFDIM, NEMBD, b1, nullptr, 1);

    // FFN down + bias + residual(xn2 fp32) -> out fp32
    tcgemm2_kernel<<<dim3(NEMBD / 128, ROWS / 128), 256, GEMM_SMEM>>>(
        p_hh, p_hl, p_w2h, p_w2l,
        out, nullptr, nullptr, ROWS, NEMBD, FFDIM, b2, p_xn2, 0);
}

// round 16
// speedup vs baseline: 4.8551x; 1.0102x over previous
#include <cuda_runtime.h>
#include <cuda_bf16.h>
#include <math.h>
#include <stdint.h>

// Problem dims
#define BATCH   8
#define SEQ     1024
#define NEMBD   1024
#define NHEAD   16
#define HSIZE   64
#define FFDIM   4096
#define ROWS    (BATCH * SEQ)          // 8192
#define QKVCOLS (3 * NEMBD)            // 3072

typedef __nv_bfloat16 bf16;

// ---------------- scratch (device globals; no allocation allowed) ----------
__device__ float g_xn1 [ROWS * NEMBD];
__device__ bf16  g_xn1h[ROWS * NEMBD];
__device__ bf16  g_xn1l[ROWS * NEMBD];
__device__ bf16  g_wqkvh[NEMBD * QKVCOLS];
__device__ bf16  g_wqkvl[NEMBD * QKVCOLS];
__device__ bf16  g_wprojh[NEMBD * NEMBD];
__device__ bf16  g_wprojl[NEMBD * NEMBD];
__device__ bf16  g_w1h[NEMBD * FFDIM];
__device__ bf16  g_w1l[NEMBD * FFDIM];
__device__ bf16  g_w2h[FFDIM * NEMBD];
__device__ bf16  g_w2l[FFDIM * NEMBD];
__device__ bf16  g_qkvh[ROWS * QKVCOLS];
__device__ bf16  g_qkvl[ROWS * QKVCOLS];
__device__ bf16  g_attnh[ROWS * NEMBD];
__device__ bf16  g_attnl[ROWS * NEMBD];
__device__ float g_x2  [ROWS * NEMBD];
__device__ float g_xn2 [ROWS * NEMBD];
__device__ bf16  g_xn2h[ROWS * NEMBD];
__device__ bf16  g_xn2l[ROWS * NEMBD];
__device__ bf16  g_hh[ROWS * FFDIM];
__device__ bf16  g_hl[ROWS * FFDIM];

// ---------------- helpers ---------------------------------------------------
__device__ __forceinline__ uint32_t smem_u32(const void* p) {
    return (uint32_t)__cvta_generic_to_shared(p);
}
__device__ __forceinline__ void cpa16(uint32_t dst, const void* src) {
    asm volatile("cp.async.cg.shared.global [%0], [%1], 16;" :: "r"(dst), "l"(src));
}
#define CP_COMMIT() asm volatile("cp.async.commit_group;")
#define CP_WAIT(n)  asm volatile("cp.async.wait_group %0;" :: "n"(n))

__device__ __forceinline__ void ldsm_x4(uint32_t* r, uint32_t addr) {
    asm volatile("ldmatrix.sync.aligned.m8n8.x4.shared.b16 {%0,%1,%2,%3}, [%4];"
                 : "=r"(r[0]), "=r"(r[1]), "=r"(r[2]), "=r"(r[3]) : "r"(addr));
}
__device__ __forceinline__ void ldsm_x2(uint32_t* r, uint32_t addr) {
    asm volatile("ldmatrix.sync.aligned.m8n8.x2.shared.b16 {%0,%1}, [%2];"
                 : "=r"(r[0]), "=r"(r[1]) : "r"(addr));
}
__device__ __forceinline__ void ldsm_x2t(uint32_t* r, uint32_t addr) {
    asm volatile("ldmatrix.sync.aligned.m8n8.x2.trans.shared.b16 {%0,%1}, [%2];"
                 : "=r"(r[0]), "=r"(r[1]) : "r"(addr));
}
__device__ __forceinline__ void mma16816(float* c, const uint32_t* a, const uint32_t* b) {
    asm volatile("mma.sync.aligned.m16n8k16.row.col.f32.bf16.bf16.f32 "
                 "{%0,%1,%2,%3}, {%4,%5,%6,%7}, {%8,%9}, {%0,%1,%2,%3};"
                 : "+f"(c[0]), "+f"(c[1]), "+f"(c[2]), "+f"(c[3])
                 : "r"(a[0]), "r"(a[1]), "r"(a[2]), "r"(a[3]),
                   "r"(b[0]), "r"(b[1]));
}
__device__ __forceinline__ uint32_t pack2(bf16 a, bf16 b) {
    return (uint32_t)__bfloat16_as_ushort(a) | ((uint32_t)__bfloat16_as_ushort(b) << 16);
}
__device__ __forceinline__ void store_split(bf16* ph, bf16* pl, float4 v) {
    bf16 hx = __float2bfloat16_rn(v.x);
    bf16 hy = __float2bfloat16_rn(v.y);
    bf16 hz = __float2bfloat16_rn(v.z);
    bf16 hw = __float2bfloat16_rn(v.w);
    bf16 lx = __float2bfloat16_rn(v.x - __bfloat162float(hx));
    bf16 ly = __float2bfloat16_rn(v.y - __bfloat162float(hy));
    bf16 lz = __float2bfloat16_rn(v.z - __bfloat162float(hz));
    bf16 lw = __float2bfloat16_rn(v.w - __bfloat162float(hw));
    *(uint2*)ph = make_uint2(pack2(hx, hy), pack2(hz, hw));
    *(uint2*)pl = make_uint2(pack2(lx, ly), pack2(lz, lw));
}
__device__ __forceinline__ float exp2_fast(float x) {
    x = fmaxf(x, -120.f);
    float z = x + 12582912.f;
    float i = z - 12582912.f;
    float f = x - i;
    float y = f * 0.6931471805599453f;
    float p = 0.008333333f;
    p = fmaf(p, y, 0.041666668f);
    p = fmaf(p, y, 0.16666667f);
    p = fmaf(p, y, 0.5f);
    p = fmaf(p, y, 1.0f);
    p = fmaf(p, y, 1.0f);
    int ii = __float_as_int(z) - 0x4B400000;
    return p * __int_as_float((ii + 127) << 23);
}

// ---------------- weight split kernels --------------------------------------
__global__ void repack_split_kernel(const float* __restrict__ wq,
                                    const float* __restrict__ wk,
                                    const float* __restrict__ wv,
                                    bf16* __restrict__ Wh, bf16* __restrict__ Wl) {
    int i = blockIdx.x * 256 + threadIdx.x;
    if (i >= NEMBD * QKVCOLS / 4) return;
    int d = (i * 4) / QKVCOLS;
    int j = (i * 4) - d * QKVCOLS;
    int sec = j >> 10;
    int within = j & 1023;
    int h = within >> 6;
    int e = within & 63;
    const float* src = (sec == 0) ? wq : (sec == 1) ? wk : wv;
    float4 v = *(const float4*)(src + ((size_t)h * NEMBD + d) * HSIZE + e);
    store_split(Wh + (size_t)d * QKVCOLS + j, Wl + (size_t)d * QKVCOLS + j, v);
}

__global__ void split_kernel(const float* __restrict__ src,
                             bf16* __restrict__ dh, bf16* __restrict__ dl, int n4) {
    int i = blockIdx.x * 256 + threadIdx.x;
    if (i >= n4) return;
    float4 v = ((const float4*)src)[i];
    store_split(dh + (size_t)i * 4, dl + (size_t)i * 4, v);
}

// ---------------- LayerNorm (fp32 + split out) ------------------------------
__global__ void ln_kernel(const float* __restrict__ in, float* __restrict__ outf,
                          bf16* __restrict__ outh, bf16* __restrict__ outl,
                          const float* __restrict__ gamma, const float* __restrict__ beta) {
    int row = blockIdx.x;
    const float4* x4 = (const float4*)(in + (size_t)row * NEMBD);
    int i = threadIdx.x;
    float4 a = x4[i];
    float s  = a.x + a.y + a.z + a.w;
    float s2 = a.x * a.x + a.y * a.y + a.z * a.z + a.w * a.w;

    #pragma unroll
    for (int o = 16; o; o >>= 1) {
        s  += __shfl_xor_sync(0xffffffffu, s, o);
        s2 += __shfl_xor_sync(0xffffffffu, s2, o);
    }
    __shared__ float sh[2][8];
    __shared__ float stats[2];
    int lane = threadIdx.x & 31, wid = threadIdx.x >> 5;
    if (lane == 0) { sh[0][wid] = s; sh[1][wid] = s2; }
    __syncthreads();
    if (threadIdx.x == 0) {
        float ts = 0.f, ts2 = 0.f;
        #pragma unroll
        for (int w = 0; w < 8; w++) { ts += sh[0][w]; ts2 += sh[1][w]; }
        float mu  = ts * (1.f / NEMBD);
        float var = ts2 * (1.f / NEMBD) - mu * mu;
        stats[0] = mu;
        stats[1] = rsqrtf(var + 1e-5f);
    }
    __syncthreads();
    float mu = stats[0], inv = stats[1];
    float4 g = ((const float4*)gamma)[i];
    float4 b = ((const float4*)beta)[i];
    float4 r;
    r.x = (a.x - mu) * inv * g.x + b.x;
    r.y = (a.y - mu) * inv * g.y + b.y;
    r.z = (a.z - mu) * inv * g.z + b.z;
    r.w = (a.w - mu) * inv * g.w + b.w;
    ((float4*)(outf + (size_t)row * NEMBD))[i] = r;
    store_split(outh + (size_t)row * NEMBD + i * 4,
                outl + (size_t)row * NEMBD + i * 4, r);
}

// ---------------- cp.async 3-stage split-bf16 GEMM --------------------------
// A_h/A_l [M,K] bf16 row-major, B_h/B_l [K,N] bf16 row-major.
// Tile 128x128, kstep 32, 3 stages, ONE __syncthreads per k-tile.
// Stage layout: As_h(128x40) As_l Bs_h(32x136) Bs_l = 37888 B
#define STG_BYTES 37888
#define GEMM_SMEM (3 * STG_BYTES)

__device__ __forceinline__ void gemm_issue(
    char* stbase,
    const bf16* __restrict__ Ah, const bf16* __restrict__ Al,
    const bf16* __restrict__ Bh, const bf16* __restrict__ Bl,
    int by, int bx, int k0, int K, int N, int tid)
{
    bf16* sAh = (bf16*)(stbase);
    bf16* sAl = (bf16*)(stbase + 10240);
    bf16* sBh = (bf16*)(stbase + 20480);
    bf16* sBl = (bf16*)(stbase + 29184);
    #pragma unroll
    for (int i = 0; i < 2; i++) {
        int idx = tid + i * 256;
        int rowA = idx >> 2, ccA = (idx & 3) * 8;
        size_t ga = (size_t)(by * 128 + rowA) * K + k0 + ccA;
        cpa16(smem_u32(sAh + rowA * 40 + ccA), Ah + ga);
        cpa16(smem_u32(sAl + rowA * 40 + ccA), Al + ga);
        int rowB = idx >> 4, ccB = (idx & 15) * 8;
        size_t gb = (size_t)(k0 + rowB) * N + bx * 128 + ccB;
        cpa16(smem_u32(sBh + rowB * 136 + ccB), Bh + gb);
        cpa16(smem_u32(sBl + rowB * 136 + ccB), Bl + gb);
    }
    CP_COMMIT();
}

__global__ void __launch_bounds__(256)
tcgemm4_kernel(const bf16* __restrict__ Ah, const bf16* __restrict__ Al,
               const bf16* __restrict__ Bh, const bf16* __restrict__ Bl,
               float* __restrict__ Cf, bf16* __restrict__ Ch, bf16* __restrict__ Cl,
               int M, int N, int K,
               const float* __restrict__ bias, const float* __restrict__ res, int relu) {
    extern __shared__ __align__(16) char smraw[];

    int bx = blockIdx.x, by = blockIdx.y;
    int tid = threadIdx.x;
    int lane = tid & 31, warp = tid >> 5;
    int wm = (warp >> 2) * 64;
    int wn = (warp & 3) * 32;

    float acc[4][4][4];
    #pragma unroll
    for (int mi = 0; mi < 4; mi++)
        #pragma unroll
        for (int ni = 0; ni < 4; ni++)
            #pragma unroll
            for (int q = 0; q < 4; q++) acc[mi][ni][q] = 0.f;

    int nt = K / 32;

    // prologue: stages 0,1 in flight
    gemm_issue(smraw,             Ah, Al, Bh, Bl, by, bx, 0,  K, N, tid);
    gemm_issue(smraw + STG_BYTES, Ah, Al, Bh, Bl, by, bx, 32, K, N, tid);

    int stg = 0;   // stage index of tile t (t % 3)

    for (int t = 0; t < nt; t++) {
        if (t + 1 < nt) { CP_WAIT(1); } else { CP_WAIT(0); }
        __syncthreads();   // tile t ready in stage stg; stage (t+2)%3 free

        if (t + 2 < nt) {
            int is = stg + 2; if (is >= 3) is -= 3;
            gemm_issue(smraw + is * STG_BYTES, Ah, Al, Bh, Bl,
                       by, bx, (t + 2) * 32, K, N, tid);
        }

        char* st = smraw + stg * STG_BYTES;
        bf16* sAh = (bf16*)(st);
        bf16* sAl = (bf16*)(st + 10240);
        bf16* sBh = (bf16*)(st + 20480);
        bf16* sBl = (bf16*)(st + 29184);

        #pragma unroll
        for (int kk = 0; kk < 2; kk++) {
            int kb = kk * 16;
            uint32_t bh[4][2], bl[4][2];
            #pragma unroll
            for (int ni = 0; ni < 4; ni++) {
                int boff = (kb + (lane & 15)) * 136 + wn + ni * 8;
                ldsm_x2t(bh[ni], smem_u32(sBh + boff));
                ldsm_x2t(bl[ni], smem_u32(sBl + boff));
            }
            #pragma unroll
            for (int mi = 0; mi < 4; mi++) {
                uint32_t ah[4], al[4];
                int aoff = (wm + mi * 16 + (lane & 15)) * 40 + kb + (lane >> 4) * 8;
                ldsm_x4(ah, smem_u32(sAh + aoff));
                ldsm_x4(al, smem_u32(sAl + aoff));
                #pragma unroll
                for (int ni = 0; ni < 4; ni++) {
                    mma16816(acc[mi][ni], ah, bh[ni]);
                    mma16816(acc[mi][ni], ah, bl[ni]);
                    mma16816(acc[mi][ni], al, bh[ni]);
                }
            }
        }

        stg++; if (stg >= 3) stg = 0;
    }

    // epilogue (direct from registers)
    int g = lane >> 2, tig = lane & 3;
    #pragma unroll
    for (int mi = 0; mi < 4; mi++) {
        #pragma unroll
        for (int ni = 0; ni < 4; ni++) {
            int r0 = by * 128 + wm + mi * 16 + g;
            int c0 = bx * 128 + wn + ni * 8 + tig * 2;
            float b0 = bias ? bias[c0] : 0.f;
            float b1 = bias ? bias[c0 + 1] : 0.f;
            float v0 = acc[mi][ni][0] + b0;
            float v1 = acc[mi][ni][1] + b1;
            float v2 = acc[mi][ni][2] + b0;
            float v3 = acc[mi][ni][3] + b1;
            if (res) {
                v0 += res[(size_t)r0 * N + c0];
                v1 += res[(size_t)r0 * N + c0 + 1];
                v2 += res[(size_t)(r0 + 8) * N + c0];
                v3 += res[(size_t)(r0 + 8) * N + c0 + 1];
            }
            if (relu) {
                v0 = fmaxf(v0, 0.f); v1 = fmaxf(v1, 0.f);
                v2 = fmaxf(v2, 0.f); v3 = fmaxf(v3, 0.f);
            }
            if (Ch) {
                bf16 h0 = __float2bfloat16_rn(v0), h1 = __float2bfloat16_rn(v1);
                bf16 h2 = __float2bfloat16_rn(v2), h3 = __float2bfloat16_rn(v3);
                *(uint32_t*)&Ch[(size_t)r0 * N + c0]       = pack2(h0, h1);
                *(uint32_t*)&Ch[(size_t)(r0 + 8) * N + c0] = pack2(h2, h3);
                *(uint32_t*)&Cl[(size_t)r0 * N + c0] =
                    pack2(__float2bfloat16_rn(v0 - __bfloat162float(h0)),
                          __float2bfloat16_rn(v1 - __bfloat162float(h1)));
                *(uint32_t*)&Cl[(size_t)(r0 + 8) * N + c0] =
                    pack2(__float2bfloat16_rn(v2 - __bfloat162float(h2)),
                          __float2bfloat16_rn(v3 - __bfloat162float(h3)));
            } else {
                Cf[(size_t)r0 * N + c0]           = v0;
                Cf[(size_t)r0 * N + c0 + 1]       = v1;
                Cf[(size_t)(r0 + 8) * N + c0]     = v2;
                Cf[(size_t)(r0 + 8) * N + c0 + 1] = v3;
            }
        }
    }
}

// ---------------- MMA flash attention (pre-split qkv in, split out) ---------
#define KPAD 72

__global__ void __launch_bounds__(128)
attn_mma2_kernel(const bf16* __restrict__ qh, const bf16* __restrict__ ql,
                 bf16* __restrict__ oh, bf16* __restrict__ ol) {
    __shared__ bf16 Ks_h[64][KPAD];
    __shared__ bf16 Ks_l[64][KPAD];
    __shared__ bf16 Vs_h[64][KPAD];
    __shared__ bf16 Vs_l[64][KPAD];

    int qt = blockIdx.x;
    int h  = blockIdx.y;
    int b  = blockIdx.z;
    int tid = threadIdx.x;
    int lane = tid & 31, w = tid >> 5;

    const float alpha = 0.125f * 1.4426950408889634f;

    {
        const bf16* qbh = qh + ((size_t)(b * SEQ + qt * 64)) * QKVCOLS + h * 64;
        const bf16* qbl = ql + ((size_t)(b * SEQ + qt * 64)) * QKVCOLS + h * 64;
        #pragma unroll
        for (int i = 0; i < 4; i++) {
            int idx = tid + i * 128;
            int row = idx >> 3, cc = (idx & 7) * 8;
            *(uint4*)&Ks_h[row][cc] = *(const uint4*)(qbh + (size_t)row * QKVCOLS + cc);
            *(uint4*)&Ks_l[row][cc] = *(const uint4*)(qbl + (size_t)row * QKVCOLS + cc);
        }
    }
    __syncthreads();

    uint32_t qa_h[4][4], qa_l[4][4];
    #pragma unroll
    for (int ks = 0; ks < 4; ks++) {
        ldsm_x4(qa_h[ks], smem_u32(&Ks_h[w * 16 + (lane & 15)][ks * 16 + (lane >> 4) * 8]));
        ldsm_x4(qa_l[ks], smem_u32(&Ks_l[w * 16 + (lane & 15)][ks * 16 + (lane >> 4) * 8]));
    }
    __syncthreads();

    float o[8][4];
    #pragma unroll
    for (int ne = 0; ne < 8; ne++)
        #pragma unroll
        for (int q = 0; q < 4; q++) o[ne][q] = 0.f;
    float m0 = -1e30f, m1 = -1e30f, l0 = 0.f, l1 = 0.f;

    int qrow0 = qt * 64 + w * 16 + (lane >> 2);

    for (int kt = 0; kt <= qt; kt++) {
        {
            size_t rb = (size_t)(b * SEQ + kt * 64);
            #pragma unroll
            for (int i = 0; i < 4; i++) {
                int idx = tid + i * 128;
                int row = idx >> 3, cc = (idx & 7) * 8;
                size_t gk = (rb + row) * QKVCOLS + NEMBD + h * 64 + cc;
                size_t gv = gk + NEMBD;
                cpa16(smem_u32(&Ks_h[row][cc]), qh + gk);
                cpa16(smem_u32(&Ks_l[row][cc]), ql + gk);
                cpa16(smem_u32(&Vs_h[row][cc]), qh + gv);
                cpa16(smem_u32(&Vs_l[row][cc]), ql + gv);
            }
            CP_COMMIT();
            CP_WAIT(0);
        }
        __syncthreads();

        float s[8][4];
        #pragma unroll
        for (int nt = 0; nt < 8; nt++) {
            s[nt][0] = s[nt][1] = s[nt][2] = s[nt][3] = 0.f;
            #pragma unroll
            for (int ks = 0; ks < 4; ks++) {
                uint32_t kh[2], kl[2];
                uint32_t addr_off = (uint32_t)((nt * 8 + (lane & 7)) * KPAD +
                                               ks * 16 + ((lane >> 3) & 1) * 8);
                ldsm_x2(kh, smem_u32(&Ks_h[0][0]) + addr_off * 2);
                ldsm_x2(kl, smem_u32(&Ks_l[0][0]) + addr_off * 2);
                mma16816(s[nt], qa_h[ks], kh);
                mma16816(s[nt], qa_h[ks], kl);
                mma16816(s[nt], qa_l[ks], kh);
            }
        }

        if (kt == qt) {
            #pragma unroll
            for (int nt = 0; nt < 8; nt++) {
                int key = kt * 64 + nt * 8 + (lane & 3) * 2;
                if (key     > qrow0)     s[nt][0] = -1e30f;
                if (key + 1 > qrow0)     s[nt][1] = -1e30f;
                if (key     > qrow0 + 8) s[nt][2] = -1e30f;
                if (key + 1 > qrow0 + 8) s[nt][3] = -1e30f;
            }
        }

        float mt0 = -1e30f, mt1 = -1e30f;
        #pragma unroll
        for (int nt = 0; nt < 8; nt++) {
            mt0 = fmaxf(mt0, fmaxf(s[nt][0], s[nt][1]));
            mt1 = fmaxf(mt1, fmaxf(s[nt][2], s[nt][3]));
        }
        mt0 = fmaxf(mt0, __shfl_xor_sync(0xffffffffu, mt0, 1));
        mt0 = fmaxf(mt0, __shfl_xor_sync(0xffffffffu, mt0, 2));
        mt1 = fmaxf(mt1, __shfl_xor_sync(0xffffffffu, mt1, 1));
        mt1 = fmaxf(mt1, __shfl_xor_sync(0xffffffffu, mt1, 2));
        float nm0 = fmaxf(m0, mt0);
        float nm1 = fmaxf(m1, mt1);
        float sc0 = exp2_fast(alpha * (m0 - nm0));
        float sc1 = exp2_fast(alpha * (m1 - nm1));
        m0 = nm0; m1 = nm1;
        float am0 = alpha * m0, am1 = alpha * m1;

        float sum0 = 0.f, sum1 = 0.f;
        #pragma unroll
        for (int nt = 0; nt < 8; nt++) {
            s[nt][0] = exp2_fast(fmaf(alpha, s[nt][0], -am0));
            s[nt][1] = exp2_fast(fmaf(alpha, s[nt][1], -am0));
            s[nt][2] = exp2_fast(fmaf(alpha, s[nt][2], -am1));
            s[nt][3] = exp2_fast(fmaf(alpha, s[nt][3], -am1));
            sum0 += s[nt][0] + s[nt][1];
            sum1 += s[nt][2] + s[nt][3];
        }
        sum0 += __shfl_xor_sync(0xffffffffu, sum0, 1);
        sum0 += __shfl_xor_sync(0xffffffffu, sum0, 2);
        sum1 += __shfl_xor_sync(0xffffffffu, sum1, 1);
        sum1 += __shfl_xor_sync(0xffffffffu, sum1, 2);
        l0 = l0 * sc0 + sum0;
        l1 = l1 * sc1 + sum1;

        #pragma unroll
        for (int ne = 0; ne < 8; ne++) {
            o[ne][0] *= sc0; o[ne][1] *= sc0;
            o[ne][2] *= sc1; o[ne][3] *= sc1;
        }

        uint32_t pa_h[4][4], pa_l[4][4];
        #pragma unroll
        for (int pk = 0; pk < 4; pk++) {
            #pragma unroll
            for (int q = 0; q < 4; q++) {
                float v0 = s[2 * pk + (q >> 1)][(q & 1) ? 2 : 0];
                float v1 = s[2 * pk + (q >> 1)][(q & 1) ? 3 : 1];
                bf16 h0 = __float2bfloat16_rn(v0);
                bf16 h1 = __float2bfloat16_rn(v1);
                pa_h[pk][q] = pack2(h0, h1);
                pa_l[pk][q] = pack2(__float2bfloat16_rn(v0 - __bfloat162float(h0)),
                                    __float2bfloat16_rn(v1 - __bfloat162float(h1)));
            }
        }

        #pragma unroll
        for (int ne = 0; ne < 8; ne++) {
            #pragma unroll
            for (int pk = 0; pk < 4; pk++) {
                uint32_t vh[2], vl[2];
                uint32_t addr_off = (uint32_t)((pk * 16 + (lane & 15)) * KPAD + ne * 8);
                ldsm_x2t(vh, smem_u32(&Vs_h[0][0]) + addr_off * 2);
                ldsm_x2t(vl, smem_u32(&Vs_l[0][0]) + addr_off * 2);
                mma16816(o[ne], pa_h[pk], vh);
                mma16816(o[ne], pa_h[pk], vl);
                mma16816(o[ne], pa_l[pk], vh);
            }
        }
        __syncthreads();
    }

    float inv0 = 1.f / l0;
    float inv1 = 1.f / l1;
    size_t r0 = (size_t)(b * SEQ + qrow0);
    int colbase = h * 64 + (lane & 3) * 2;
    #pragma unroll
    for (int ne = 0; ne < 8; ne++) {
        int col = colbase + ne * 8;
        float v0 = o[ne][0] * inv0, v1 = o[ne][1] * inv0;
        float v2 = o[ne][2] * inv1, v3 = o[ne][3] * inv1;
        bf16 h0 = __float2bfloat16_rn(v0), h1 = __float2bfloat16_rn(v1);
        bf16 h2 = __float2bfloat16_rn(v2), h3 = __float2bfloat16_rn(v3);
        *(uint32_t*)&oh[r0 * NEMBD + col]       = pack2(h0, h1);
        *(uint32_t*)&oh[(r0 + 8) * NEMBD + col] = pack2(h2, h3);
        *(uint32_t*)&ol[r0 * NEMBD + col] =
            pack2(__float2bfloat16_rn(v0 - __bfloat162float(h0)),
                  __float2bfloat16_rn(v1 - __bfloat162float(h1)));
        *(uint32_t*)&ol[(r0 + 8) * NEMBD + col] =
            pack2(__float2bfloat16_rn(v2 - __bfloat162float(h2)),
                  __float2bfloat16_rn(v3 - __bfloat162float(h3)));
    }
}

// ---------------- launch ----------------------------------------------------
extern "C" void kernel_launch(void* const* d_in, const int* in_sizes, int n_in,
                              void* d_out, int out_size) {
    const float* x      = (const float*)d_in[0];
    const float* wq     = (const float*)d_in[1];
    const float* wk     = (const float*)d_in[2];
    const float* wv     = (const float*)d_in[3];
    const float* w_proj = (const float*)d_in[4];
    const float* b_proj = (const float*)d_in[5];
    const float* w1     = (const float*)d_in[6];
    const float* b1     = (const float*)d_in[7];
    const float* w2     = (const float*)d_in[8];
    const float* b2     = (const float*)d_in[9];
    const float* g1     = (const float*)d_in[10];
    const float* be1    = (const float*)d_in[11];
    const float* g2     = (const float*)d_in[12];
    const float* be2    = (const float*)d_in[13];
    float* out = (float*)d_out;

    float *p_xn1, *p_x2, *p_xn2;
    bf16 *p_xn1h, *p_xn1l, *p_wqkvh, *p_wqkvl, *p_wprojh, *p_wprojl;
    bf16 *p_w1h, *p_w1l, *p_w2h, *p_w2l, *p_qkvh, *p_qkvl;
    bf16 *p_attnh, *p_attnl, *p_xn2h, *p_xn2l, *p_hh, *p_hl;
    cudaGetSymbolAddress((void**)&p_xn1,   g_xn1);
    cudaGetSymbolAddress((void**)&p_xn1h,  g_xn1h);
    cudaGetSymbolAddress((void**)&p_xn1l,  g_xn1l);
    cudaGetSymbolAddress((void**)&p_wqkvh, g_wqkvh);
    cudaGetSymbolAddress((void**)&p_wqkvl, g_wqkvl);
    cudaGetSymbolAddress((void**)&p_wprojh, g_wprojh);
    cudaGetSymbolAddress((void**)&p_wprojl, g_wprojl);
    cudaGetSymbolAddress((void**)&p_w1h,   g_w1h);
    cudaGetSymbolAddress((void**)&p_w1l,   g_w1l);
    cudaGetSymbolAddress((void**)&p_w2h,   g_w2h);
    cudaGetSymbolAddress((void**)&p_w2l,   g_w2l);
    cudaGetSymbolAddress((void**)&p_qkvh,  g_qkvh);
    cudaGetSymbolAddress((void**)&p_qkvl,  g_qkvl);
    cudaGetSymbolAddress((void**)&p_attnh, g_attnh);
    cudaGetSymbolAddress((void**)&p_attnl, g_attnl);
    cudaGetSymbolAddress((void**)&p_x2,    g_x2);
    cudaGetSymbolAddress((void**)&p_xn2,   g_xn2);
    cudaGetSymbolAddress((void**)&p_xn2h,  g_xn2h);
    cudaGetSymbolAddress((void**)&p_xn2l,  g_xn2l);
    cudaGetSymbolAddress((void**)&p_hh,    g_hh);
    cudaGetSymbolAddress((void**)&p_hl,    g_hl);

    cudaFuncSetAttribute(tcgemm4_kernel,
                         cudaFuncAttributeMaxDynamicSharedMemorySize, GEMM_SMEM);

    // weights -> split bf16 (once per launch)
    repack_split_kernel<<<(NEMBD * QKVCOLS / 4 + 255) / 256, 256>>>(wq, wk, wv, p_wqkvh, p_wqkvl);
    split_kernel<<<(NEMBD * NEMBD / 4 + 255) / 256, 256>>>(w_proj, p_wprojh, p_wprojl, NEMBD * NEMBD / 4);
    split_kernel<<<(NEMBD * FFDIM / 4 + 255) / 256, 256>>>(w1, p_w1h, p_w1l, NEMBD * FFDIM / 4);
    split_kernel<<<(FFDIM * NEMBD / 4 + 255) / 256, 256>>>(w2, p_w2h, p_w2l, FFDIM * NEMBD / 4);

    // LN1 (fp32 + split)
    ln_kernel<<<ROWS, 256>>>(x, p_xn1, p_xn1h, p_xn1l, g1, be1);

    // QKV projection -> split qkv
    tcgemm4_kernel<<<dim3(QKVCOLS / 128, ROWS / 128), 256, GEMM_SMEM>>>(
        p_xn1h, p_xn1l, p_wqkvh, p_wqkvl,
        nullptr, p_qkvh, p_qkvl, ROWS, QKVCOLS, NEMBD, nullptr, nullptr, 0);

    // attention -> split attn
    attn_mma2_kernel<<<dim3(SEQ / 64, NHEAD, BATCH), 128>>>(p_qkvh, p_qkvl, p_attnh, p_attnl);

    // output projection + bias + residual(xn1 fp32) -> x2 fp32
    tcgemm4_kernel<<<dim3(NEMBD / 128, ROWS / 128), 256, GEMM_SMEM>>>(
        p_attnh, p_attnl, p_wprojh, p_wprojl,
        p_x2, nullptr, nullptr, ROWS, NEMBD, NEMBD, b_proj, p_xn1, 0);

    // LN2 (fp32 + split)
    ln_kernel<<<ROWS, 256>>>(p_x2, p_xn2, p_xn2h, p_xn2l, g2, be2);

    // FFN up + bias + relu -> split h
    tcgemm4_kernel<<<dim3(FFDIM / 128, ROWS / 128), 256, GEMM_SMEM>>>(
        p_xn2h, p_xn2l, p_w1h, p_w1l,
        nullptr, p_hh, p_hl, ROWS, FFDIM, NEMBD, b1, nullptr, 1);

    // FFN down + bias + residual(xn2 fp32) -> out fp32
    tcgemm4_kernel<<<dim3(NEMBD / 128, ROWS / 128), 256, GEMM_SMEM>>>(
        p_hh, p_hl, p_w2h, p_w2l,
        out, nullptr, nullptr, ROWS, NEMBD, FFDIM, b2, p_xn2, 0);
}